// round 12
// baseline (speedup 1.0000x reference)
#include <cuda_runtime.h>
#include <cuda_bf16.h>
#include <math.h>
#include <stdint.h>
#include <string.h>

// Problem constants (shape-fixed by the dataset)
#define H    128
#define KEIG 32
#define NF   (9*H)           // 1152
#define MAXN 50048           // N=50000 rounded up to 64
#define MAXE 600064          // E=600000
#define AVG_D_LOG 2.5649493574615367f   // log(13)

// ---- static device scratch (no allocation allowed) ----
__device__ float g_x[(size_t)MAXN*H];               // diffusion_out
__device__ __nv_bfloat16 g_featsh[(size_t)MAXN*NF]; // [N,9H] concat features (bf16)
__device__ __nv_bfloat16 g_Wph[NF*H];               // W_post in bf16
__device__ __nv_bfloat16 g_Wlh[H*H];                // W_last lower half (rows H..2H) in bf16
__device__ float g_coeff[KEIG*H];
__device__ int   g_count[MAXN];
__device__ int   g_rowstart[MAXN+1];
__device__ int   g_cursor[MAXN];
__device__ int   g_eord[MAXE];
__device__ int   g_bsum[64];

// ---- persistent side stream + events ----
static cudaStream_t g_s1 = nullptr;
static cudaEvent_t  g_evFork = nullptr, g_evJoin = nullptr;
namespace {
struct StreamInit {
    StreamInit() {
        if (cudaStreamCreateWithFlags(&g_s1, cudaStreamNonBlocking) != cudaSuccess) g_s1 = nullptr;
        if (cudaEventCreateWithFlags(&g_evFork, cudaEventDisableTiming) != cudaSuccess) g_evFork = nullptr;
        if (cudaEventCreateWithFlags(&g_evJoin, cudaEventDisableTiming) != cudaSuccess) g_evJoin = nullptr;
    }
};
static StreamInit g_si;
}

// ---------------------------------------------------------------
// 0) prep: zero coeff + counters, convert W_post/W_last-lower -> bf16
// ---------------------------------------------------------------
__global__ void k_prep(const float* __restrict__ Wp, const float* __restrict__ Wl, int N) {
    int i = blockIdx.x*blockDim.x + threadIdx.x;
    if (i < KEIG*H) g_coeff[i] = 0.f;
    if (i < N)      g_count[i] = 0;
    if (i < NF*H)   g_Wph[i] = __float2bfloat16(Wp[i]);
    if (i < H*H)    g_Wlh[i] = __float2bfloat16(Wl[(size_t)H*H + i]);
}

// ---------------------------------------------------------------
// 1) CSR build: count edges per dst
// ---------------------------------------------------------------
__global__ void k_count(const int* __restrict__ ei, int E) {
    int e = blockIdx.x*blockDim.x + threadIdx.x;
    if (e < E) atomicAdd(&g_count[ei[E + e]], 1);
}

// 2a) per-1024-chunk local exclusive scan
__global__ void k_scan1(int N) {
    __shared__ int sh[1024];
    int t = threadIdx.x;
    int i = blockIdx.x*1024 + t;
    int v = (i < N) ? g_count[i] : 0;
    sh[t] = v;
    __syncthreads();
    for (int off = 1; off < 1024; off <<= 1) {
        int u = (t >= off) ? sh[t - off] : 0;
        __syncthreads();
        sh[t] += u;
        __syncthreads();
    }
    if (i < N) g_rowstart[i] = sh[t] - v;     // local exclusive
    if (t == 1023) g_bsum[blockIdx.x] = sh[1023];
}

// 2b) fused block-offset scan + materialize rowstart/cursor
__global__ void k_scan23(int nb, int N) {
    __shared__ int sh[64];
    int t = threadIdx.x;
    if (t < 64) sh[t] = (t < nb) ? g_bsum[t] : 0;
    __syncthreads();
    if (t == 0) {
        int acc = 0;
#pragma unroll
        for (int i = 0; i < 64; i++) { int v = sh[i]; sh[i] = acc; acc += v; }
        if (blockIdx.x == 0) g_rowstart[N] = acc;   // total = E
    }
    __syncthreads();
    int boff = sh[blockIdx.x];
    int i = blockIdx.x*1024 + t;
    if (i < N) {
        int v = g_rowstart[i] + boff;
        g_rowstart[i] = v;
        g_cursor[i]   = v;
    }
}

// 3) scatter edge ids into CSR order
__global__ void k_scatter(const int* __restrict__ ei, int E) {
    int e = blockIdx.x*blockDim.x + threadIdx.x;
    if (e < E) {
        int d = ei[E + e];
        int p = atomicAdd(&g_cursor[d], 1);
        g_eord[p] = e;
    }
}

// ---------------------------------------------------------------
// 4) coeff[K,H] = eigvec^T @ (deg * node_fts)
// ---------------------------------------------------------------
__global__ void k_coeff(const float* __restrict__ nf, const float* __restrict__ deg,
                        const float* __restrict__ vec, int N) {
    __shared__ float xs[8][H];
    __shared__ float vs[8][KEIG];
    int t  = threadIdx.x;
    int kk = t & 31;
    int hb = (t >> 5) << 4;           // 0..112 step 16
    float acc[16];
#pragma unroll
    for (int j = 0; j < 16; j++) acc[j] = 0.f;
    int nbase = blockIdx.x * 128;
    for (int stage = 0; stage < 16; stage++) {
        int n0 = nbase + stage * 8;
        for (int i = t; i < 8*H; i += 256) {
            int r = i >> 7, c = i & 127;
            int n = n0 + r;
            xs[r][c] = (n < N) ? nf[(size_t)n*H + c] * deg[n] : 0.f;
        }
        for (int i = t; i < 8*KEIG; i += 256) {
            int r = i >> 5, c = i & 31;
            int n = n0 + r;
            vs[r][c] = (n < N) ? vec[(size_t)n*KEIG + c] : 0.f;
        }
        __syncthreads();
#pragma unroll
        for (int r = 0; r < 8; r++) {
            float v = vs[r][kk];
#pragma unroll
            for (int j = 0; j < 16; j++) acc[j] += v * xs[r][hb + j];
        }
        __syncthreads();
    }
#pragma unroll
    for (int j = 0; j < 16; j++) atomicAdd(&g_coeff[kk*H + hb + j], acc[j]);
}

// ---------------------------------------------------------------
// 6) x = eigvec @ (coeff * exp(-lam*softplus(t))), 32 nodes/block
// ---------------------------------------------------------------
__global__ void k_x(const float* __restrict__ vec, const float* __restrict__ lam,
                    const float* __restrict__ dt, int N) {
    __shared__ float c2[KEIG*H];       // 16 KB
    __shared__ float vs[32][KEIG+1];
    __shared__ float s_t[H];
    __shared__ float s_lam[KEIG];
    int t = threadIdx.x;
    if (t < H) {
        float x = dt[t];
        s_t[t] = (x > 20.f) ? x : log1pf(expf(x));
    }
    if (t < KEIG) s_lam[t] = lam[t];
    __syncthreads();
    for (int i = t; i < KEIG*H; i += 256) {
        int k = i >> 7, h = i & 127;
        c2[i] = g_coeff[i] * expf(-s_lam[k] * s_t[h]);
    }
    int n0 = blockIdx.x * 32;
    for (int i = t; i < 32*KEIG; i += 256) {
        int r = i >> 5, c = i & 31;
        int n = n0 + r;
        vs[r][c] = (n < N) ? vec[(size_t)n*KEIG + c] : 0.f;
    }
    __syncthreads();
    int h = t & 127;
    int g = t >> 7;                    // 0..1, 16 nodes each
    float acc[16];
#pragma unroll
    for (int i = 0; i < 16; i++) acc[i] = 0.f;
#pragma unroll
    for (int k = 0; k < KEIG; k++) {
        float c = c2[k*H + h];
#pragma unroll
        for (int i = 0; i < 16; i++) acc[i] += vs[g*16 + i][k] * c;
    }
#pragma unroll
    for (int i = 0; i < 16; i++) {
        int n = n0 + g*16 + i;
        if (n < N) g_x[(size_t)n*H + h] = acc[i];
    }
}

// ---------------------------------------------------------------
// 7) aggregation: warp-per-node, float4 per lane, shfl-broadcast,
//    2x unrolled edge loop (round-9 known-good)
// ---------------------------------------------------------------
__device__ __forceinline__ void st_bf16x4(__nv_bfloat16* p, float4 v) {
    __nv_bfloat162 lo = __floats2bfloat162_rn(v.x, v.y);
    __nv_bfloat162 hi = __floats2bfloat162_rn(v.z, v.w);
    uint2 u;
    memcpy(&u.x, &lo, 4);
    memcpy(&u.y, &hi, 4);
    *(uint2*)p = u;
}

__global__ __launch_bounds__(256) void k_agg(
        const int* __restrict__ ei, const float* __restrict__ Fn,
        const float* __restrict__ Fdig, const float* __restrict__ degv, int N) {
    int warp = threadIdx.x >> 5, lane = threadIdx.x & 31;
    int n = blockIdx.x * 8 + warp;
    if (n >= N) return;
    int beg = g_rowstart[n], end = g_rowstart[n+1];
    const float4* xrow = (const float4*)&g_x[(size_t)n*H];
    float4 xn = xrow[lane];

    float4 s  = {0.f,0.f,0.f,0.f};
    float4 mx = {-INFINITY,-INFINITY,-INFINITY,-INFINITY};
    float4 ws = {0.f,0.f,0.f,0.f};
    float4 fs = {0.f,0.f,0.f,0.f};
    float wsum = 0.f;

    for (int jb = beg; jb < end; jb += 32) {
        int cnt = min(32, end - jb);
        int   srcl = 0;
        float Fl   = 0.f;
        if (jb + lane < end) {
            int e = g_eord[jb + lane];
            srcl = ei[e];
            Fl   = Fn[e];
        }
        int jj = 0;
        for (; jj + 2 <= cnt; jj += 2) {
            int   src0 = __shfl_sync(0xffffffffu, srcl, jj);
            int   src1 = __shfl_sync(0xffffffffu, srcl, jj + 1);
            float F0   = __shfl_sync(0xffffffffu, Fl,   jj);
            float F1   = __shfl_sync(0xffffffffu, Fl,   jj + 1);
            float4 m0 = *(const float4*)&g_x[(size_t)src0*H + lane*4];
            float4 m1 = *(const float4*)&g_x[(size_t)src1*H + lane*4];
            float w0 = fabsf(F0), w1 = fabsf(F1);
            s.x += m0.x + m1.x; s.y += m0.y + m1.y;
            s.z += m0.z + m1.z; s.w += m0.w + m1.w;
            mx.x = fmaxf(mx.x, fmaxf(m0.x, m1.x));
            mx.y = fmaxf(mx.y, fmaxf(m0.y, m1.y));
            mx.z = fmaxf(mx.z, fmaxf(m0.z, m1.z));
            mx.w = fmaxf(mx.w, fmaxf(m0.w, m1.w));
            ws.x += w0*m0.x + w1*m1.x; ws.y += w0*m0.y + w1*m1.y;
            ws.z += w0*m0.z + w1*m1.z; ws.w += w0*m0.w + w1*m1.w;
            fs.x += F0*m0.x + F1*m1.x; fs.y += F0*m0.y + F1*m1.y;
            fs.z += F0*m0.z + F1*m1.z; fs.w += F0*m0.w + F1*m1.w;
            wsum += w0 + w1;
        }
        if (jj < cnt) {
            int   src = __shfl_sync(0xffffffffu, srcl, jj);
            float F   = __shfl_sync(0xffffffffu, Fl,   jj);
            float4 m0 = *(const float4*)&g_x[(size_t)src*H + lane*4];
            float w = fabsf(F);
            s.x += m0.x; s.y += m0.y; s.z += m0.z; s.w += m0.w;
            mx.x = fmaxf(mx.x, m0.x); mx.y = fmaxf(mx.y, m0.y);
            mx.z = fmaxf(mx.z, m0.z); mx.w = fmaxf(mx.w, m0.w);
            ws.x += w*m0.x; ws.y += w*m0.y; ws.z += w*m0.z; ws.w += w*m0.w;
            fs.x += F*m0.x; fs.y += F*m0.y; fs.z += F*m0.z; fs.w += F*m0.w;
            wsum += w;
        }
    }

    float deg = degv[n];
    float inv_deg = 1.f / deg;
    float inv_w   = 1.f / (wsum + 1e-8f);
    float fd  = Fdig[n];
    float amp = log1pf(deg) / AVG_D_LOG;
    bool has = (end > beg);

    float4 mean  = { s.x*inv_deg, s.y*inv_deg, s.z*inv_deg, s.w*inv_deg };
    float4 mxo   = { has ? mx.x : 0.f, has ? mx.y : 0.f,
                     has ? mx.z : 0.f, has ? mx.w : 0.f };
    float4 dirav = { ws.x*inv_w, ws.y*inv_w, ws.z*inv_w, ws.w*inv_w };
    float4 dirdx = { fs.x - fd*xn.x, fs.y - fd*xn.y,
                     fs.z - fd*xn.z, fs.w - fd*xn.w };

    __nv_bfloat16* base = &g_featsh[(size_t)n*NF + lane*4];
    st_bf16x4(base + 0*H, xn);
    st_bf16x4(base + 1*H, mean);
    st_bf16x4(base + 2*H, mxo);
    st_bf16x4(base + 3*H, dirav);
    st_bf16x4(base + 4*H, dirdx);
    float4 t;
    t = make_float4(mean.x*amp,  mean.y*amp,  mean.z*amp,  mean.w*amp);  st_bf16x4(base + 5*H, t);
    t = make_float4(mxo.x*amp,   mxo.y*amp,   mxo.z*amp,   mxo.w*amp);   st_bf16x4(base + 6*H, t);
    t = make_float4(dirav.x*amp, dirav.y*amp, dirav.z*amp, dirav.w*amp); st_bf16x4(base + 7*H, t);
    t = make_float4(dirdx.x*amp, dirdx.y*amp, dirdx.z*amp, dirdx.w*amp); st_bf16x4(base + 8*H, t);
}

// ---------------------------------------------------------------
// MMA helpers
// ---------------------------------------------------------------
__device__ __forceinline__ void ldm_x4(uint32_t* r, uint32_t addr) {
    asm volatile("ldmatrix.sync.aligned.m8n8.x4.shared.b16 {%0,%1,%2,%3}, [%4];"
        : "=r"(r[0]), "=r"(r[1]), "=r"(r[2]), "=r"(r[3]) : "r"(addr));
}
__device__ __forceinline__ void ldm_x4_t(uint32_t* r, uint32_t addr) {
    asm volatile("ldmatrix.sync.aligned.m8n8.x4.trans.shared.b16 {%0,%1,%2,%3}, [%4];"
        : "=r"(r[0]), "=r"(r[1]), "=r"(r[2]), "=r"(r[3]) : "r"(addr));
}
__device__ __forceinline__ void mma_bf16(float* d, const uint32_t* a, const uint32_t* b) {
    asm volatile(
        "mma.sync.aligned.m16n8k16.row.col.f32.bf16.bf16.f32 "
        "{%0,%1,%2,%3}, {%4,%5,%6,%7}, {%8,%9}, {%0,%1,%2,%3};"
        : "+f"(d[0]), "+f"(d[1]), "+f"(d[2]), "+f"(d[3])
        : "r"(a[0]), "r"(a[1]), "r"(a[2]), "r"(a[3]), "r"(b[0]), "r"(b[1]));
}
__device__ __forceinline__ void mma_tf32(float* d, const uint32_t* a, const uint32_t* b) {
    asm volatile(
        "mma.sync.aligned.m16n8k8.row.col.f32.tf32.tf32.f32 "
        "{%0,%1,%2,%3}, {%4,%5,%6,%7}, {%8,%9}, {%0,%1,%2,%3};"
        : "+f"(d[0]), "+f"(d[1]), "+f"(d[2]), "+f"(d[3])
        : "r"(a[0]), "r"(a[1]), "r"(a[2]), "r"(a[3]), "r"(b[0]), "r"(b[1]));
}
__device__ __forceinline__ uint32_t f2tf32(float x) {
    uint32_t o;
    asm("cvt.rna.tf32.f32 %0, %1;" : "=r"(o) : "f"(x));
    return o;
}
__device__ __forceinline__ void cp16(void* smem, const void* gmem) {
    uint32_t s = (uint32_t)__cvta_generic_to_shared(smem);
    asm volatile("cp.async.cg.shared.global [%0], [%1], 16;" :: "r"(s), "l"(gmem));
}

// ---------------------------------------------------------------
// 8) FUSED MLP:
//    phase 1: dgn = relu(feats @ W_post + b_post)*norm_n  (bf16 TC,
//             3-stage cp.async pipeline) -> smem (bf16)
//    phase 2a: acc = x @ Wl_top (tf32 TC, from gmem)
//    phase 2b: acc += dgn @ Wl_bot (bf16 TC, dgn from smem)
//    out = node_fts + acc + b_last
// ---------------------------------------------------------------
#define AST 40    // phase-1 A stride (bf16)
#define BST 136   // phase-1 B / Ds / Bs3 stride (bf16)
#define A2ST 36   // phase-2a A stride (tf32 words)
#define B2ST 136  // phase-2a B stride (tf32 words)

// dynamic smem layout (bytes)
#define SM_P1A 0                        // 3*128*AST*2  = 30720
#define SM_P1B 30720                    // 3*32*BST*2   = 26112  (end 56832)
#define SM_DS  0                        // 128*BST*2    = 34816  (after phase 1)
#define SM_AS2 34816                    // 128*A2ST*4   = 18432  (end 53248)
#define SM_BS2 53248                    // 32*B2ST*4    = 17408  (end 70656)
#define SM_BS3 34816                    // 128*BST*2    = 34816  (end 69632, after 2a)
#define SM_TOTAL 70656

__global__ __launch_bounds__(256) void k_mlp(
        const float* __restrict__ bp, const float* __restrict__ normn,
        const float* __restrict__ Wl, const float* __restrict__ bl,
        const float* __restrict__ nfts, float* __restrict__ out, int N) {
    extern __shared__ char smem[];
    __nv_bfloat16* As  = (__nv_bfloat16*)(smem + SM_P1A);   // [3][128*AST]
    __nv_bfloat16* Bs  = (__nv_bfloat16*)(smem + SM_P1B);   // [3][32*BST]
    __nv_bfloat16* Ds  = (__nv_bfloat16*)(smem + SM_DS);    // [128*BST]
    uint32_t*      As2 = (uint32_t*)     (smem + SM_AS2);   // [128*A2ST]
    uint32_t*      Bs2 = (uint32_t*)     (smem + SM_BS2);   // [32*B2ST]
    __nv_bfloat16* Bs3 = (__nv_bfloat16*)(smem + SM_BS3);   // [128*BST]

    int t = threadIdx.x;
    int warp = t >> 5, lane = t & 31;
    int m0 = blockIdx.x * 128;
    int wm = warp >> 1;            // 0..3 -> 32 rows each
    int wn = warp & 1;             // 0..1 -> 64 cols each
    int lrow = lane & 15, lseg = (lane >> 4) * 8;
    int qrow = lane >> 2;          // 0..7
    int qcol = (lane & 3) * 2;     // 0,2,4,6

    float acc[2][8][4];
#pragma unroll
    for (int i = 0; i < 2; i++)
#pragma unroll
        for (int j = 0; j < 8; j++)
#pragma unroll
            for (int c = 0; c < 4; c++) acc[i][j][c] = 0.f;

    // ---------------- phase 1: feats @ W_post ----------------
    int arow = t >> 1, acol = (t & 1) * 16;    // A: 128 rows x 32 cols
    int brow = t >> 3, bcol = (t & 7) * 16;    // B: 32 rows x 128 cols
    const __nv_bfloat16* agbase = &g_featsh[(size_t)(m0 + arow)*NF + acol];
    const __nv_bfloat16* bgbase = &g_Wph[(size_t)brow*H + bcol];

#define P1_STAGE(s, k0) do {                                             \
        cp16(&As[(s)*128*AST + arow*AST + acol],     agbase + (k0));     \
        cp16(&As[(s)*128*AST + arow*AST + acol + 8], agbase + (k0) + 8); \
        cp16(&Bs[(s)*32*BST + brow*BST + bcol],      bgbase + (size_t)(k0)*H);     \
        cp16(&Bs[(s)*32*BST + brow*BST + bcol + 8],  bgbase + (size_t)(k0)*H + 8); \
        asm volatile("cp.async.commit_group;");                          \
    } while (0)

    const int NIT = NF / 32;   // 36
    P1_STAGE(0, 0);
    P1_STAGE(1, 32);
    int st = 0;
    for (int it = 0; it < NIT; it++) {
        if (it + 2 < NIT) {
            int s2 = st + 2; if (s2 >= 3) s2 -= 3;
            P1_STAGE(s2, (it + 2) * 32);
            asm volatile("cp.async.wait_group 2;");
        } else if (it + 1 < NIT) {
            asm volatile("cp.async.wait_group 1;");
        } else {
            asm volatile("cp.async.wait_group 0;");
        }
        __syncthreads();
#pragma unroll
        for (int ks = 0; ks < 2; ks++) {
            int kk = ks * 16;
            uint32_t a[2][4], b[4][4];
#pragma unroll
            for (int tm = 0; tm < 2; tm++) {
                uint32_t addr = (uint32_t)__cvta_generic_to_shared(
                    &As[st*128*AST + (wm*32 + tm*16 + lrow)*AST + kk + lseg]);
                ldm_x4(a[tm], addr);
            }
#pragma unroll
            for (int tn = 0; tn < 4; tn++) {
                uint32_t addr = (uint32_t)__cvta_generic_to_shared(
                    &Bs[st*32*BST + (kk + lrow)*BST + wn*64 + tn*16 + lseg]);
                ldm_x4_t(b[tn], addr);
            }
#pragma unroll
            for (int tm = 0; tm < 2; tm++)
#pragma unroll
                for (int tn = 0; tn < 4; tn++) {
                    mma_bf16(acc[tm][tn*2],     a[tm], &b[tn][0]);
                    mma_bf16(acc[tm][tn*2 + 1], a[tm], &b[tn][2]);
                }
        }
        __syncthreads();
        if (++st == 3) st = 0;
    }
#undef P1_STAGE

    // epilogue 1: bias + relu + graph-norm -> Ds (bf16, stride BST)
#pragma unroll
    for (int tm = 0; tm < 2; tm++) {
#pragma unroll
        for (int tnn = 0; tnn < 8; tnn++) {
            int col = wn*64 + tnn*8 + qcol;
            float bb0 = bp[col], bb1 = bp[col + 1];
            int r0 = m0 + wm*32 + tm*16 + qrow;
            int r1 = r0 + 8;
            int lr0 = wm*32 + tm*16 + qrow;
            float nn0 = (r0 < N) ? normn[r0] : 0.f;
            float nn1 = (r1 < N) ? normn[r1] : 0.f;
            __nv_bfloat162 v0 = __floats2bfloat162_rn(
                fmaxf(acc[tm][tnn][0] + bb0, 0.f) * nn0,
                fmaxf(acc[tm][tnn][1] + bb1, 0.f) * nn0);
            __nv_bfloat162 v1 = __floats2bfloat162_rn(
                fmaxf(acc[tm][tnn][2] + bb0, 0.f) * nn1,
                fmaxf(acc[tm][tnn][3] + bb1, 0.f) * nn1);
            *(__nv_bfloat162*)&Ds[lr0*BST + col]       = v0;
            *(__nv_bfloat162*)&Ds[(lr0 + 8)*BST + col] = v1;
        }
    }

    // reset accumulators for phase 2
#pragma unroll
    for (int i = 0; i < 2; i++)
#pragma unroll
        for (int j = 0; j < 8; j++)
#pragma unroll
            for (int c = 0; c < 4; c++) acc[i][j][c] = 0.f;
    __syncthreads();

    // ---------------- phase 2a: x @ Wl_top (tf32) ----------------
    int lr = lane >> 2, lc = lane & 3;
    for (int k0 = 0; k0 < H; k0 += 32) {
        const float* asrcp = &g_x[(size_t)(m0 + arow)*H + k0 + acol];
#pragma unroll
        for (int q = 0; q < 4; q++) {
            float4 v = *(const float4*)(asrcp + q*4);
            uint32_t* d = &As2[arow*A2ST + acol + q*4];
            d[0] = f2tf32(v.x); d[1] = f2tf32(v.y);
            d[2] = f2tf32(v.z); d[3] = f2tf32(v.w);
        }
        const float* bsrcp = &Wl[(size_t)(k0 + brow)*H + bcol];
#pragma unroll
        for (int q = 0; q < 4; q++) {
            float4 v = *(const float4*)(bsrcp + q*4);
            uint32_t* d = &Bs2[brow*B2ST + bcol + q*4];
            d[0] = f2tf32(v.x); d[1] = f2tf32(v.y);
            d[2] = f2tf32(v.z); d[3] = f2tf32(v.w);
        }
        __syncthreads();
#pragma unroll
        for (int ks = 0; ks < 4; ks++) {
            int ko = ks * 8;
            uint32_t a[2][4], b[8][2];
#pragma unroll
            for (int tm = 0; tm < 2; tm++) {
                int r = (wm*32 + tm*16 + lr) * A2ST;
                a[tm][0] = As2[r + ko + lc];
                a[tm][1] = As2[r + 8*A2ST + ko + lc];
                a[tm][2] = As2[r + ko + 4 + lc];
                a[tm][3] = As2[r + 8*A2ST + ko + 4 + lc];
            }
#pragma unroll
            for (int tn = 0; tn < 8; tn++) {
                int nn = wn*64 + tn*8 + lr;
                b[tn][0] = Bs2[(ko + lc)*B2ST + nn];
                b[tn][1] = Bs2[(ko + 4 + lc)*B2ST + nn];
            }
#pragma unroll
            for (int tm = 0; tm < 2; tm++)
#pragma unroll
                for (int tn = 0; tn < 8; tn++)
                    mma_tf32(acc[tm][tn], a[tm], b[tn]);
        }
        __syncthreads();
    }

    // ---------------- phase 2b: dgn @ Wl_bot (bf16, Ds in smem) ----------------
    // stage Wl_bot (bf16, 128x128 = 16 chunks of 8 bf16 per row) into Bs3
    for (int i = t; i < 128*16; i += 256) {
        int r = i >> 4, seg = (i & 15) * 8;
        cp16(&Bs3[r*BST + seg], &g_Wlh[r*H + seg]);
    }
    asm volatile("cp.async.commit_group;");
    asm volatile("cp.async.wait_group 0;");
    __syncthreads();

#pragma unroll
    for (int kk2 = 0; kk2 < 128; kk2 += 16) {
        uint32_t a[2][4], b[4][4];
#pragma unroll
        for (int tm = 0; tm < 2; tm++) {
            uint32_t addr = (uint32_t)__cvta_generic_to_shared(
                &Ds[(wm*32 + tm*16 + lrow)*BST + kk2 + lseg]);
            ldm_x4(a[tm], addr);
        }
#pragma unroll
        for (int tn = 0; tn < 4; tn++) {
            uint32_t addr = (uint32_t)__cvta_generic_to_shared(
                &Bs3[(kk2 + lrow)*BST + wn*64 + tn*16 + lseg]);
            ldm_x4_t(b[tn], addr);
        }
#pragma unroll
        for (int tm = 0; tm < 2; tm++)
#pragma unroll
            for (int tn = 0; tn < 4; tn++) {
                mma_bf16(acc[tm][tn*2],     a[tm], &b[tn][0]);
                mma_bf16(acc[tm][tn*2 + 1], a[tm], &b[tn][2]);
            }
    }

    // final epilogue: out = node_fts + acc + b_last
#pragma unroll
    for (int tm = 0; tm < 2; tm++) {
#pragma unroll
        for (int tn = 0; tn < 8; tn++) {
            int col = wn*64 + tn*8 + qcol;
            float bb0 = bl[col], bb1 = bl[col + 1];
            int r0 = m0 + wm*32 + tm*16 + qrow;
            int r1 = r0 + 8;
            if (r0 < N) {
                float2 rv = *(const float2*)&nfts[(size_t)r0*H + col];
                float2 v = { rv.x + acc[tm][tn][0] + bb0,
                             rv.y + acc[tm][tn][1] + bb1 };
                *(float2*)&out[(size_t)r0*H + col] = v;
            }
            if (r1 < N) {
                float2 rv = *(const float2*)&nfts[(size_t)r1*H + col];
                float2 v = { rv.x + acc[tm][tn][2] + bb0,
                             rv.y + acc[tm][tn][3] + bb1 };
                *(float2*)&out[(size_t)r1*H + col] = v;
            }
        }
    }
}

// ---------------------------------------------------------------
extern "C" void kernel_launch(void* const* d_in, const int* in_sizes, int n_in,
                              void* d_out, int out_size) {
    const float* node_fts = (const float*)d_in[0];
    // d_in[1] = edge_fts (unused)
    const int*   ei       = (const int*)  d_in[2];   // [2,E]: src row then dst row
    const float* Fn       = (const float*)d_in[3];   // [E,1]
    const float* Fdig     = (const float*)d_in[4];   // [N,1]
    const float* degv     = (const float*)d_in[5];   // [N,1]
    // d_in[6] node_deg_mat, d_in[7] lap_mat (unused)
    const float* lam      = (const float*)d_in[8];   // [K]
    const float* vec      = (const float*)d_in[9];   // [N,K]
    int o = (n_in >= 18) ? 1 : 0;
    const float* normn = (const float*)d_in[10 + o]; // [N,1]
    const float* dt    = (const float*)d_in[12 + o]; // [H]
    const float* Wp    = (const float*)d_in[13 + o]; // [9H,H]
    const float* bp    = (const float*)d_in[14 + o]; // [H]
    const float* Wl    = (const float*)d_in[15 + o]; // [2H,H]
    const float* bl    = (const float*)d_in[16 + o]; // [H]

    int E = in_sizes[3];   // F_norm_edge has E elements
    int N = in_sizes[4];   // F_dig has N elements
    float* out = (float*)d_out;

    // opt-in to >48KB dynamic smem (idempotent; not a stream op)
    cudaFuncSetAttribute(k_mlp, cudaFuncAttributeMaxDynamicSharedMemorySize, SM_TOTAL);

    const int TB = 256;
    int nb = (N + 1023) / 1024;

    bool mt = (g_s1 != nullptr) && (g_evFork != nullptr) && (g_evJoin != nullptr);
    cudaStream_t sA = mt ? g_s1 : (cudaStream_t)0;

    // common root
    k_prep    <<<(NF*H + TB - 1)/TB, TB>>>(Wp, Wl, N);

    if (mt) {
        cudaEventRecord(g_evFork, (cudaStream_t)0);
        cudaStreamWaitEvent(sA, g_evFork, 0);
    }

    // chain A (CSR build) — side stream
    k_count   <<<(E + TB - 1)/TB, TB, 0, sA>>>(ei, E);
    k_scan1   <<<nb, 1024, 0, sA>>>(N);
    k_scan23  <<<nb, 1024, 0, sA>>>(nb, N);
    k_scatter <<<(E + TB - 1)/TB, TB, 0, sA>>>(ei, E);
    if (mt) cudaEventRecord(g_evJoin, sA);

    // chain B (spectral diffusion) — main stream
    k_coeff   <<<(N + 127)/128, 256>>>(node_fts, degv, vec, N);
    k_x       <<<(N + 31)/32, 256>>>(vec, lam, dt, N);

    if (mt) cudaStreamWaitEvent((cudaStream_t)0, g_evJoin, 0);

    // join: aggregation + fused MLP
    k_agg     <<<(N + 7)/8, 256>>>(ei, Fn, Fdig, degv, N);
    k_mlp     <<<(N + 127)/128, 256, SM_TOTAL>>>(bp, normn, Wl, bl, node_fts, out, N);
}

// round 13
// speedup vs baseline: 1.3880x; 1.3880x over previous
#include <cuda_runtime.h>
#include <cuda_bf16.h>
#include <math.h>
#include <stdint.h>
#include <string.h>

// Problem constants (shape-fixed by the dataset)
#define H    128
#define KEIG 32
#define NF   (9*H)           // 1152
#define MAXN 50048           // N=50000 rounded up to 64
#define MAXE 600064          // E=600000
#define AVG_D_LOG 2.5649493574615367f   // log(13)

// ---- static device scratch (no allocation allowed) ----
__device__ float g_x[(size_t)MAXN*H];               // diffusion_out
__device__ __nv_bfloat16 g_featsh[(size_t)MAXN*NF]; // [N,9H] concat features (bf16)
__device__ __nv_bfloat16 g_Wph[NF*H];               // W_post in bf16
__device__ __nv_bfloat16 g_Wlh[H*H];                // W_last lower half (rows H..2H) in bf16
__device__ float g_coeff[KEIG*H];
__device__ int   g_count[MAXN];
__device__ int   g_rowstart[MAXN+1];
__device__ int   g_cursor[MAXN];
__device__ int   g_eord[MAXE];
__device__ int   g_bsum[64];

// ---- persistent side stream + events ----
static cudaStream_t g_s1 = nullptr;
static cudaEvent_t  g_evFork = nullptr, g_evJoin = nullptr;
namespace {
struct StreamInit {
    StreamInit() {
        if (cudaStreamCreateWithFlags(&g_s1, cudaStreamNonBlocking) != cudaSuccess) g_s1 = nullptr;
        if (cudaEventCreateWithFlags(&g_evFork, cudaEventDisableTiming) != cudaSuccess) g_evFork = nullptr;
        if (cudaEventCreateWithFlags(&g_evJoin, cudaEventDisableTiming) != cudaSuccess) g_evJoin = nullptr;
    }
};
static StreamInit g_si;
}

// ---------------------------------------------------------------
// 0a) critical-path prep: zero coeff only (gates chain B)
// ---------------------------------------------------------------
__global__ void k_prep_main() {
    int i = blockIdx.x*blockDim.x + threadIdx.x;
    if (i < KEIG*H) g_coeff[i] = 0.f;
}

// 0b) side-stream prep: zero counters + convert weights to bf16
__global__ void k_prep_side(const float* __restrict__ Wp, const float* __restrict__ Wl, int N) {
    int i = blockIdx.x*blockDim.x + threadIdx.x;
    if (i < N)    g_count[i] = 0;
    if (i < NF*H) g_Wph[i] = __float2bfloat16(Wp[i]);
    if (i < H*H)  g_Wlh[i] = __float2bfloat16(Wl[(size_t)H*H + i]);
}

// ---------------------------------------------------------------
// 1) CSR build: count edges per dst
// ---------------------------------------------------------------
__global__ void k_count(const int* __restrict__ ei, int E) {
    int e = blockIdx.x*blockDim.x + threadIdx.x;
    if (e < E) atomicAdd(&g_count[ei[E + e]], 1);
}

// 2a) per-1024-chunk local exclusive scan
__global__ void k_scan1(int N) {
    __shared__ int sh[1024];
    int t = threadIdx.x;
    int i = blockIdx.x*1024 + t;
    int v = (i < N) ? g_count[i] : 0;
    sh[t] = v;
    __syncthreads();
    for (int off = 1; off < 1024; off <<= 1) {
        int u = (t >= off) ? sh[t - off] : 0;
        __syncthreads();
        sh[t] += u;
        __syncthreads();
    }
    if (i < N) g_rowstart[i] = sh[t] - v;     // local exclusive
    if (t == 1023) g_bsum[blockIdx.x] = sh[1023];
}

// 2b) fused block-offset scan + materialize rowstart/cursor
__global__ void k_scan23(int nb, int N) {
    __shared__ int sh[64];
    int t = threadIdx.x;
    if (t < 64) sh[t] = (t < nb) ? g_bsum[t] : 0;
    __syncthreads();
    if (t == 0) {
        int acc = 0;
#pragma unroll
        for (int i = 0; i < 64; i++) { int v = sh[i]; sh[i] = acc; acc += v; }
        if (blockIdx.x == 0) g_rowstart[N] = acc;   // total = E
    }
    __syncthreads();
    int boff = sh[blockIdx.x];
    int i = blockIdx.x*1024 + t;
    if (i < N) {
        int v = g_rowstart[i] + boff;
        g_rowstart[i] = v;
        g_cursor[i]   = v;
    }
}

// 3) scatter edge ids into CSR order
__global__ void k_scatter(const int* __restrict__ ei, int E) {
    int e = blockIdx.x*blockDim.x + threadIdx.x;
    if (e < E) {
        int d = ei[E + e];
        int p = atomicAdd(&g_cursor[d], 1);
        g_eord[p] = e;
    }
}

// ---------------------------------------------------------------
// 4) coeff[K,H] = eigvec^T @ (deg * node_fts)
// ---------------------------------------------------------------
__global__ void k_coeff(const float* __restrict__ nf, const float* __restrict__ deg,
                        const float* __restrict__ vec, int N) {
    __shared__ float xs[8][H];
    __shared__ float vs[8][KEIG];
    int t  = threadIdx.x;
    int kk = t & 31;
    int hb = (t >> 5) << 4;           // 0..112 step 16
    float acc[16];
#pragma unroll
    for (int j = 0; j < 16; j++) acc[j] = 0.f;
    int nbase = blockIdx.x * 128;
    for (int stage = 0; stage < 16; stage++) {
        int n0 = nbase + stage * 8;
        for (int i = t; i < 8*H; i += 256) {
            int r = i >> 7, c = i & 127;
            int n = n0 + r;
            xs[r][c] = (n < N) ? nf[(size_t)n*H + c] * deg[n] : 0.f;
        }
        for (int i = t; i < 8*KEIG; i += 256) {
            int r = i >> 5, c = i & 31;
            int n = n0 + r;
            vs[r][c] = (n < N) ? vec[(size_t)n*KEIG + c] : 0.f;
        }
        __syncthreads();
#pragma unroll
        for (int r = 0; r < 8; r++) {
            float v = vs[r][kk];
#pragma unroll
            for (int j = 0; j < 16; j++) acc[j] += v * xs[r][hb + j];
        }
        __syncthreads();
    }
#pragma unroll
    for (int j = 0; j < 16; j++) atomicAdd(&g_coeff[kk*H + hb + j], acc[j]);
}

// ---------------------------------------------------------------
// 6) x = eigvec @ (coeff * exp(-lam*softplus(t))), 32 nodes/block
// ---------------------------------------------------------------
__global__ void k_x(const float* __restrict__ vec, const float* __restrict__ lam,
                    const float* __restrict__ dt, int N) {
    __shared__ float c2[KEIG*H];       // 16 KB
    __shared__ float vs[32][KEIG+1];
    __shared__ float s_t[H];
    __shared__ float s_lam[KEIG];
    int t = threadIdx.x;
    if (t < H) {
        float x = dt[t];
        s_t[t] = (x > 20.f) ? x : log1pf(expf(x));
    }
    if (t < KEIG) s_lam[t] = lam[t];
    __syncthreads();
    for (int i = t; i < KEIG*H; i += 256) {
        int k = i >> 7, h = i & 127;
        c2[i] = g_coeff[i] * expf(-s_lam[k] * s_t[h]);
    }
    int n0 = blockIdx.x * 32;
    for (int i = t; i < 32*KEIG; i += 256) {
        int r = i >> 5, c = i & 31;
        int n = n0 + r;
        vs[r][c] = (n < N) ? vec[(size_t)n*KEIG + c] : 0.f;
    }
    __syncthreads();
    int h = t & 127;
    int g = t >> 7;                    // 0..1, 16 nodes each
    float acc[16];
#pragma unroll
    for (int i = 0; i < 16; i++) acc[i] = 0.f;
#pragma unroll
    for (int k = 0; k < KEIG; k++) {
        float c = c2[k*H + h];
#pragma unroll
        for (int i = 0; i < 16; i++) acc[i] += vs[g*16 + i][k] * c;
    }
#pragma unroll
    for (int i = 0; i < 16; i++) {
        int n = n0 + g*16 + i;
        if (n < N) g_x[(size_t)n*H + h] = acc[i];
    }
}

// ---------------------------------------------------------------
// 7) aggregation: warp-per-node, float4 per lane, shfl-broadcast,
//    2x unrolled edge loop (round-9 known-good)
// ---------------------------------------------------------------
__device__ __forceinline__ void st_bf16x4(__nv_bfloat16* p, float4 v) {
    __nv_bfloat162 lo = __floats2bfloat162_rn(v.x, v.y);
    __nv_bfloat162 hi = __floats2bfloat162_rn(v.z, v.w);
    uint2 u;
    memcpy(&u.x, &lo, 4);
    memcpy(&u.y, &hi, 4);
    *(uint2*)p = u;
}

__global__ __launch_bounds__(256) void k_agg(
        const int* __restrict__ ei, const float* __restrict__ Fn,
        const float* __restrict__ Fdig, const float* __restrict__ degv, int N) {
    int warp = threadIdx.x >> 5, lane = threadIdx.x & 31;
    int n = blockIdx.x * 8 + warp;
    if (n >= N) return;
    int beg = g_rowstart[n], end = g_rowstart[n+1];
    const float4* xrow = (const float4*)&g_x[(size_t)n*H];
    float4 xn = xrow[lane];

    float4 s  = {0.f,0.f,0.f,0.f};
    float4 mx = {-INFINITY,-INFINITY,-INFINITY,-INFINITY};
    float4 ws = {0.f,0.f,0.f,0.f};
    float4 fs = {0.f,0.f,0.f,0.f};
    float wsum = 0.f;

    for (int jb = beg; jb < end; jb += 32) {
        int cnt = min(32, end - jb);
        int   srcl = 0;
        float Fl   = 0.f;
        if (jb + lane < end) {
            int e = g_eord[jb + lane];
            srcl = ei[e];
            Fl   = Fn[e];
        }
        int jj = 0;
        for (; jj + 2 <= cnt; jj += 2) {
            int   src0 = __shfl_sync(0xffffffffu, srcl, jj);
            int   src1 = __shfl_sync(0xffffffffu, srcl, jj + 1);
            float F0   = __shfl_sync(0xffffffffu, Fl,   jj);
            float F1   = __shfl_sync(0xffffffffu, Fl,   jj + 1);
            float4 m0 = *(const float4*)&g_x[(size_t)src0*H + lane*4];
            float4 m1 = *(const float4*)&g_x[(size_t)src1*H + lane*4];
            float w0 = fabsf(F0), w1 = fabsf(F1);
            s.x += m0.x + m1.x; s.y += m0.y + m1.y;
            s.z += m0.z + m1.z; s.w += m0.w + m1.w;
            mx.x = fmaxf(mx.x, fmaxf(m0.x, m1.x));
            mx.y = fmaxf(mx.y, fmaxf(m0.y, m1.y));
            mx.z = fmaxf(mx.z, fmaxf(m0.z, m1.z));
            mx.w = fmaxf(mx.w, fmaxf(m0.w, m1.w));
            ws.x += w0*m0.x + w1*m1.x; ws.y += w0*m0.y + w1*m1.y;
            ws.z += w0*m0.z + w1*m1.z; ws.w += w0*m0.w + w1*m1.w;
            fs.x += F0*m0.x + F1*m1.x; fs.y += F0*m0.y + F1*m1.y;
            fs.z += F0*m0.z + F1*m1.z; fs.w += F0*m0.w + F1*m1.w;
            wsum += w0 + w1;
        }
        if (jj < cnt) {
            int   src = __shfl_sync(0xffffffffu, srcl, jj);
            float F   = __shfl_sync(0xffffffffu, Fl,   jj);
            float4 m0 = *(const float4*)&g_x[(size_t)src*H + lane*4];
            float w = fabsf(F);
            s.x += m0.x; s.y += m0.y; s.z += m0.z; s.w += m0.w;
            mx.x = fmaxf(mx.x, m0.x); mx.y = fmaxf(mx.y, m0.y);
            mx.z = fmaxf(mx.z, m0.z); mx.w = fmaxf(mx.w, m0.w);
            ws.x += w*m0.x; ws.y += w*m0.y; ws.z += w*m0.z; ws.w += w*m0.w;
            fs.x += F*m0.x; fs.y += F*m0.y; fs.z += F*m0.z; fs.w += F*m0.w;
            wsum += w;
        }
    }

    float deg = degv[n];
    float inv_deg = 1.f / deg;
    float inv_w   = 1.f / (wsum + 1e-8f);
    float fd  = Fdig[n];
    float amp = log1pf(deg) / AVG_D_LOG;
    bool has = (end > beg);

    float4 mean  = { s.x*inv_deg, s.y*inv_deg, s.z*inv_deg, s.w*inv_deg };
    float4 mxo   = { has ? mx.x : 0.f, has ? mx.y : 0.f,
                     has ? mx.z : 0.f, has ? mx.w : 0.f };
    float4 dirav = { ws.x*inv_w, ws.y*inv_w, ws.z*inv_w, ws.w*inv_w };
    float4 dirdx = { fs.x - fd*xn.x, fs.y - fd*xn.y,
                     fs.z - fd*xn.z, fs.w - fd*xn.w };

    __nv_bfloat16* base = &g_featsh[(size_t)n*NF + lane*4];
    st_bf16x4(base + 0*H, xn);
    st_bf16x4(base + 1*H, mean);
    st_bf16x4(base + 2*H, mxo);
    st_bf16x4(base + 3*H, dirav);
    st_bf16x4(base + 4*H, dirdx);
    float4 t;
    t = make_float4(mean.x*amp,  mean.y*amp,  mean.z*amp,  mean.w*amp);  st_bf16x4(base + 5*H, t);
    t = make_float4(mxo.x*amp,   mxo.y*amp,   mxo.z*amp,   mxo.w*amp);   st_bf16x4(base + 6*H, t);
    t = make_float4(dirav.x*amp, dirav.y*amp, dirav.z*amp, dirav.w*amp); st_bf16x4(base + 7*H, t);
    t = make_float4(dirdx.x*amp, dirdx.y*amp, dirdx.z*amp, dirdx.w*amp); st_bf16x4(base + 8*H, t);
}

// ---------------------------------------------------------------
// MMA helpers
// ---------------------------------------------------------------
__device__ __forceinline__ void ldm_x4(uint32_t* r, uint32_t addr) {
    asm volatile("ldmatrix.sync.aligned.m8n8.x4.shared.b16 {%0,%1,%2,%3}, [%4];"
        : "=r"(r[0]), "=r"(r[1]), "=r"(r[2]), "=r"(r[3]) : "r"(addr));
}
__device__ __forceinline__ void ldm_x4_t(uint32_t* r, uint32_t addr) {
    asm volatile("ldmatrix.sync.aligned.m8n8.x4.trans.shared.b16 {%0,%1,%2,%3}, [%4];"
        : "=r"(r[0]), "=r"(r[1]), "=r"(r[2]), "=r"(r[3]) : "r"(addr));
}
__device__ __forceinline__ void mma_bf16(float* d, const uint32_t* a, const uint32_t* b) {
    asm volatile(
        "mma.sync.aligned.m16n8k16.row.col.f32.bf16.bf16.f32 "
        "{%0,%1,%2,%3}, {%4,%5,%6,%7}, {%8,%9}, {%0,%1,%2,%3};"
        : "+f"(d[0]), "+f"(d[1]), "+f"(d[2]), "+f"(d[3])
        : "r"(a[0]), "r"(a[1]), "r"(a[2]), "r"(a[3]), "r"(b[0]), "r"(b[1]));
}
__device__ __forceinline__ void mma_tf32(float* d, const uint32_t* a, const uint32_t* b) {
    asm volatile(
        "mma.sync.aligned.m16n8k8.row.col.f32.tf32.tf32.f32 "
        "{%0,%1,%2,%3}, {%4,%5,%6,%7}, {%8,%9}, {%0,%1,%2,%3};"
        : "+f"(d[0]), "+f"(d[1]), "+f"(d[2]), "+f"(d[3])
        : "r"(a[0]), "r"(a[1]), "r"(a[2]), "r"(a[3]), "r"(b[0]), "r"(b[1]));
}
__device__ __forceinline__ uint32_t f2tf32(float x) {
    uint32_t o;
    asm("cvt.rna.tf32.f32 %0, %1;" : "=r"(o) : "f"(x));
    return o;
}
__device__ __forceinline__ void cp16(void* smem, const void* gmem) {
    uint32_t s = (uint32_t)__cvta_generic_to_shared(smem);
    asm volatile("cp.async.cg.shared.global [%0], [%1], 16;" :: "r"(s), "l"(gmem));
}

// ---------------------------------------------------------------
// 8) FUSED MLP (round-9 known-good 2-stage pipeline):
//    phase 1: dgn = relu(feats @ W_post + b_post)*norm_n -> smem (bf16)
//    phase 2a: acc = x @ Wl_top (tf32 TC, from gmem)
//    phase 2b: acc += dgn @ Wl_bot (bf16 TC, dgn from smem)
//    out = node_fts + acc + b_last
// ---------------------------------------------------------------
#define AST 40    // phase-1 A stride (bf16)
#define BST 136   // phase-1 B / Ds / Bs3 stride (bf16)
#define A2ST 36   // phase-2a A stride (tf32 words)
#define B2ST 136  // phase-2a B stride (tf32 words)

// dynamic smem layout (bytes)
#define SM_P1A 0                        // 2*128*AST*2  = 20480
#define SM_P1B 20480                    // 2*32*BST*2   = 17408  (end 37888)
#define SM_DS  0                        // 128*BST*2    = 34816  (after phase 1)
#define SM_AS2 34816                    // 128*A2ST*4   = 18432  (end 53248)
#define SM_BS2 53248                    // 32*B2ST*4    = 17408  (end 70656)
#define SM_BS3 34816                    // 128*BST*2    = 34816  (end 69632, after 2a)
#define SM_TOTAL 70656

__global__ __launch_bounds__(256) void k_mlp(
        const float* __restrict__ bp, const float* __restrict__ normn,
        const float* __restrict__ Wl, const float* __restrict__ bl,
        const float* __restrict__ nfts, float* __restrict__ out, int N) {
    extern __shared__ char smem[];
    __nv_bfloat16* As  = (__nv_bfloat16*)(smem + SM_P1A);   // [2][128*AST]
    __nv_bfloat16* Bs  = (__nv_bfloat16*)(smem + SM_P1B);   // [2][32*BST]
    __nv_bfloat16* Ds  = (__nv_bfloat16*)(smem + SM_DS);    // [128*BST]
    uint32_t*      As2 = (uint32_t*)     (smem + SM_AS2);   // [128*A2ST]
    uint32_t*      Bs2 = (uint32_t*)     (smem + SM_BS2);   // [32*B2ST]
    __nv_bfloat16* Bs3 = (__nv_bfloat16*)(smem + SM_BS3);   // [128*BST]

    int t = threadIdx.x;
    int warp = t >> 5, lane = t & 31;
    int m0 = blockIdx.x * 128;
    int wm = warp >> 1;            // 0..3 -> 32 rows each
    int wn = warp & 1;             // 0..1 -> 64 cols each
    int lrow = lane & 15, lseg = (lane >> 4) * 8;
    int qrow = lane >> 2;          // 0..7
    int qcol = (lane & 3) * 2;     // 0,2,4,6

    float acc[2][8][4];
#pragma unroll
    for (int i = 0; i < 2; i++)
#pragma unroll
        for (int j = 0; j < 8; j++)
#pragma unroll
            for (int c = 0; c < 4; c++) acc[i][j][c] = 0.f;

    // ---------------- phase 1: feats @ W_post ----------------
    int arow = t >> 1, acol = (t & 1) * 16;    // A: 128 rows x 32 cols
    int brow = t >> 3, bcol = (t & 7) * 16;    // B: 32 rows x 128 cols
    const __nv_bfloat16* agbase = &g_featsh[(size_t)(m0 + arow)*NF + acol];
    const __nv_bfloat16* bgbase = &g_Wph[(size_t)brow*H + bcol];

#define P1_STAGE(s, k0) do {                                             \
        cp16(&As[(s)*128*AST + arow*AST + acol],     agbase + (k0));     \
        cp16(&As[(s)*128*AST + arow*AST + acol + 8], agbase + (k0) + 8); \
        cp16(&Bs[(s)*32*BST + brow*BST + bcol],      bgbase + (size_t)(k0)*H);     \
        cp16(&Bs[(s)*32*BST + brow*BST + bcol + 8],  bgbase + (size_t)(k0)*H + 8); \
        asm volatile("cp.async.commit_group;");                          \
    } while (0)

    const int NIT = NF / 32;   // 36
    P1_STAGE(0, 0);
    for (int it = 0; it < NIT; it++) {
        int st = it & 1;
        if (it + 1 < NIT) {
            P1_STAGE(1 - st, (it + 1) * 32);
            asm volatile("cp.async.wait_group 1;");
        } else {
            asm volatile("cp.async.wait_group 0;");
        }
        __syncthreads();
#pragma unroll
        for (int ks = 0; ks < 2; ks++) {
            int kk = ks * 16;
            uint32_t a[2][4], b[4][4];
#pragma unroll
            for (int tm = 0; tm < 2; tm++) {
                uint32_t addr = (uint32_t)__cvta_generic_to_shared(
                    &As[st*128*AST + (wm*32 + tm*16 + lrow)*AST + kk + lseg]);
                ldm_x4(a[tm], addr);
            }
#pragma unroll
            for (int tn = 0; tn < 4; tn++) {
                uint32_t addr = (uint32_t)__cvta_generic_to_shared(
                    &Bs[st*32*BST + (kk + lrow)*BST + wn*64 + tn*16 + lseg]);
                ldm_x4_t(b[tn], addr);
            }
#pragma unroll
            for (int tm = 0; tm < 2; tm++)
#pragma unroll
                for (int tn = 0; tn < 4; tn++) {
                    mma_bf16(acc[tm][tn*2],     a[tm], &b[tn][0]);
                    mma_bf16(acc[tm][tn*2 + 1], a[tm], &b[tn][2]);
                }
        }
        __syncthreads();
    }
#undef P1_STAGE

    // epilogue 1: bias + relu + graph-norm -> Ds (bf16, stride BST)
#pragma unroll
    for (int tm = 0; tm < 2; tm++) {
#pragma unroll
        for (int tnn = 0; tnn < 8; tnn++) {
            int col = wn*64 + tnn*8 + qcol;
            float bb0 = bp[col], bb1 = bp[col + 1];
            int r0 = m0 + wm*32 + tm*16 + qrow;
            int r1 = r0 + 8;
            int lr0 = wm*32 + tm*16 + qrow;
            float nn0 = (r0 < N) ? normn[r0] : 0.f;
            float nn1 = (r1 < N) ? normn[r1] : 0.f;
            __nv_bfloat162 v0 = __floats2bfloat162_rn(
                fmaxf(acc[tm][tnn][0] + bb0, 0.f) * nn0,
                fmaxf(acc[tm][tnn][1] + bb1, 0.f) * nn0);
            __nv_bfloat162 v1 = __floats2bfloat162_rn(
                fmaxf(acc[tm][tnn][2] + bb0, 0.f) * nn1,
                fmaxf(acc[tm][tnn][3] + bb1, 0.f) * nn1);
            *(__nv_bfloat162*)&Ds[lr0*BST + col]       = v0;
            *(__nv_bfloat162*)&Ds[(lr0 + 8)*BST + col] = v1;
        }
    }

    // reset accumulators for phase 2
#pragma unroll
    for (int i = 0; i < 2; i++)
#pragma unroll
        for (int j = 0; j < 8; j++)
#pragma unroll
            for (int c = 0; c < 4; c++) acc[i][j][c] = 0.f;
    __syncthreads();

    // ---------------- phase 2a: x @ Wl_top (tf32) ----------------
    int lr = lane >> 2, lc = lane & 3;
    for (int k0 = 0; k0 < H; k0 += 32) {
        const float* asrcp = &g_x[(size_t)(m0 + arow)*H + k0 + acol];
#pragma unroll
        for (int q = 0; q < 4; q++) {
            float4 v = *(const float4*)(asrcp + q*4);
            uint32_t* d = &As2[arow*A2ST + acol + q*4];
            d[0] = f2tf32(v.x); d[1] = f2tf32(v.y);
            d[2] = f2tf32(v.z); d[3] = f2tf32(v.w);
        }
        const float* bsrcp = &Wl[(size_t)(k0 + brow)*H + bcol];
#pragma unroll
        for (int q = 0; q < 4; q++) {
            float4 v = *(const float4*)(bsrcp + q*4);
            uint32_t* d = &Bs2[brow*B2ST + bcol + q*4];
            d[0] = f2tf32(v.x); d[1] = f2tf32(v.y);
            d[2] = f2tf32(v.z); d[3] = f2tf32(v.w);
        }
        __syncthreads();
#pragma unroll
        for (int ks = 0; ks < 4; ks++) {
            int ko = ks * 8;
            uint32_t a[2][4], b[8][2];
#pragma unroll
            for (int tm = 0; tm < 2; tm++) {
                int r = (wm*32 + tm*16 + lr) * A2ST;
                a[tm][0] = As2[r + ko + lc];
                a[tm][1] = As2[r + 8*A2ST + ko + lc];
                a[tm][2] = As2[r + ko + 4 + lc];
                a[tm][3] = As2[r + 8*A2ST + ko + 4 + lc];
            }
#pragma unroll
            for (int tn = 0; tn < 8; tn++) {
                int nn = wn*64 + tn*8 + lr;
                b[tn][0] = Bs2[(ko + lc)*B2ST + nn];
                b[tn][1] = Bs2[(ko + 4 + lc)*B2ST + nn];
            }
#pragma unroll
            for (int tm = 0; tm < 2; tm++)
#pragma unroll
                for (int tn = 0; tn < 8; tn++)
                    mma_tf32(acc[tm][tn], a[tm], b[tn]);
        }
        __syncthreads();
    }

    // ---------------- phase 2b: dgn @ Wl_bot (bf16, Ds in smem) ----------------
    // stage Wl_bot (bf16, 128x128 = 16 chunks of 8 bf16 per row) into Bs3
    for (int i = t; i < 128*16; i += 256) {
        int r = i >> 4, seg = (i & 15) * 8;
        cp16(&Bs3[r*BST + seg], &g_Wlh[r*H + seg]);
    }
    asm volatile("cp.async.commit_group;");
    asm volatile("cp.async.wait_group 0;");
    __syncthreads();

#pragma unroll
    for (int kk2 = 0; kk2 < 128; kk2 += 16) {
        uint32_t a[2][4], b[4][4];
#pragma unroll
        for (int tm = 0; tm < 2; tm++) {
            uint32_t addr = (uint32_t)__cvta_generic_to_shared(
                &Ds[(wm*32 + tm*16 + lrow)*BST + kk2 + lseg]);
            ldm_x4(a[tm], addr);
        }
#pragma unroll
        for (int tn = 0; tn < 4; tn++) {
            uint32_t addr = (uint32_t)__cvta_generic_to_shared(
                &Bs3[(kk2 + lrow)*BST + wn*64 + tn*16 + lseg]);
            ldm_x4_t(b[tn], addr);
        }
#pragma unroll
        for (int tm = 0; tm < 2; tm++)
#pragma unroll
            for (int tn = 0; tn < 4; tn++) {
                mma_bf16(acc[tm][tn*2],     a[tm], &b[tn][0]);
                mma_bf16(acc[tm][tn*2 + 1], a[tm], &b[tn][2]);
            }
    }

    // final epilogue: out = node_fts + acc + b_last
#pragma unroll
    for (int tm = 0; tm < 2; tm++) {
#pragma unroll
        for (int tn = 0; tn < 8; tn++) {
            int col = wn*64 + tn*8 + qcol;
            float bb0 = bl[col], bb1 = bl[col + 1];
            int r0 = m0 + wm*32 + tm*16 + qrow;
            int r1 = r0 + 8;
            if (r0 < N) {
                float2 rv = *(const float2*)&nfts[(size_t)r0*H + col];
                float2 v = { rv.x + acc[tm][tn][0] + bb0,
                             rv.y + acc[tm][tn][1] + bb1 };
                *(float2*)&out[(size_t)r0*H + col] = v;
            }
            if (r1 < N) {
                float2 rv = *(const float2*)&nfts[(size_t)r1*H + col];
                float2 v = { rv.x + acc[tm][tn][2] + bb0,
                             rv.y + acc[tm][tn][3] + bb1 };
                *(float2*)&out[(size_t)r1*H + col] = v;
            }
        }
    }
}

// ---------------------------------------------------------------
extern "C" void kernel_launch(void* const* d_in, const int* in_sizes, int n_in,
                              void* d_out, int out_size) {
    const float* node_fts = (const float*)d_in[0];
    // d_in[1] = edge_fts (unused)
    const int*   ei       = (const int*)  d_in[2];   // [2,E]: src row then dst row
    const float* Fn       = (const float*)d_in[3];   // [E,1]
    const float* Fdig     = (const float*)d_in[4];   // [N,1]
    const float* degv     = (const float*)d_in[5];   // [N,1]
    // d_in[6] node_deg_mat, d_in[7] lap_mat (unused)
    const float* lam      = (const float*)d_in[8];   // [K]
    const float* vec      = (const float*)d_in[9];   // [N,K]
    int o = (n_in >= 18) ? 1 : 0;
    const float* normn = (const float*)d_in[10 + o]; // [N,1]
    const float* dt    = (const float*)d_in[12 + o]; // [H]
    const float* Wp    = (const float*)d_in[13 + o]; // [9H,H]
    const float* bp    = (const float*)d_in[14 + o]; // [H]
    const float* Wl    = (const float*)d_in[15 + o]; // [2H,H]
    const float* bl    = (const float*)d_in[16 + o]; // [H]

    int E = in_sizes[3];   // F_norm_edge has E elements
    int N = in_sizes[4];   // F_dig has N elements
    float* out = (float*)d_out;

    // opt-in to >48KB dynamic smem (idempotent; not a stream op)
    cudaFuncSetAttribute(k_mlp, cudaFuncAttributeMaxDynamicSharedMemorySize, SM_TOTAL);

    const int TB = 256;
    int nb = (N + 1023) / 1024;

    bool mt = (g_s1 != nullptr) && (g_evFork != nullptr) && (g_evJoin != nullptr);
    cudaStream_t sA = mt ? g_s1 : (cudaStream_t)0;

    if (mt) {
        // fork immediately; side stream does its own prep + CSR chain
        cudaEventRecord(g_evFork, (cudaStream_t)0);
        cudaStreamWaitEvent(sA, g_evFork, 0);
    }

    // chain A (side stream): prep (counters + weight cvt) + CSR build
    k_prep_side<<<(NF*H + TB - 1)/TB, TB, 0, sA>>>(Wp, Wl, N);
    k_count    <<<(E + TB - 1)/TB, TB, 0, sA>>>(ei, E);
    k_scan1    <<<nb, 1024, 0, sA>>>(N);
    k_scan23   <<<nb, 1024, 0, sA>>>(nb, N);
    k_scatter  <<<(E + TB - 1)/TB, TB, 0, sA>>>(ei, E);
    if (mt) cudaEventRecord(g_evJoin, sA);

    // chain B (main stream): tiny coeff-zero + spectral diffusion
    k_prep_main<<<(KEIG*H + TB - 1)/TB, TB>>>();
    k_coeff    <<<(N + 127)/128, 256>>>(node_fts, degv, vec, N);
    k_x        <<<(N + 31)/32, 256>>>(vec, lam, dt, N);

    if (mt) cudaStreamWaitEvent((cudaStream_t)0, g_evJoin, 0);

    // join: aggregation + fused MLP
    k_agg      <<<(N + 7)/8, 256>>>(ei, Fn, Fdig, degv, N);
    k_mlp      <<<(N + 127)/128, 256, SM_TOTAL>>>(bp, normn, Wl, bl, node_fts, out, N);
}

// round 14
// speedup vs baseline: 1.4024x; 1.0103x over previous
#include <cuda_runtime.h>
#include <cuda_bf16.h>
#include <math.h>
#include <stdint.h>
#include <string.h>

// Problem constants (shape-fixed by the dataset)
#define H    128
#define KEIG 32
#define NF   (9*H)           // 1152
#define MAXN 50048           // N=50000 rounded up to 64
#define MAXE 600064          // E=600000
#define AVG_D_LOG 2.5649493574615367f   // log(13)

// ---- static device scratch (no allocation allowed) ----
__device__ float g_x[(size_t)MAXN*H];               // diffusion_out
__device__ __nv_bfloat16 g_featsh[(size_t)MAXN*NF]; // [N,9H] concat features (bf16)
__device__ __nv_bfloat16 g_Wph[NF*H];               // W_post in bf16
__device__ __nv_bfloat16 g_Wlh[H*H];                // W_last lower half (rows H..2H) in bf16
__device__ float g_coeff[KEIG*H];
__device__ int   g_count[MAXN];
__device__ int   g_rowstart[MAXN+1];
__device__ int   g_cursor[MAXN];
__device__ int   g_eord[MAXE];
__device__ int   g_bsum[64];

// ---- persistent side stream + events ----
static cudaStream_t g_s1 = nullptr;
static cudaEvent_t  g_evFork = nullptr, g_evJoin = nullptr;
static cudaEvent_t  g_evA = nullptr, g_evJoin2 = nullptr;
namespace {
struct StreamInit {
    StreamInit() {
        if (cudaStreamCreateWithFlags(&g_s1, cudaStreamNonBlocking) != cudaSuccess) g_s1 = nullptr;
        if (cudaEventCreateWithFlags(&g_evFork, cudaEventDisableTiming) != cudaSuccess) g_evFork = nullptr;
        if (cudaEventCreateWithFlags(&g_evJoin, cudaEventDisableTiming) != cudaSuccess) g_evJoin = nullptr;
        if (cudaEventCreateWithFlags(&g_evA, cudaEventDisableTiming) != cudaSuccess) g_evA = nullptr;
        if (cudaEventCreateWithFlags(&g_evJoin2, cudaEventDisableTiming) != cudaSuccess) g_evJoin2 = nullptr;
    }
};
static StreamInit g_si;
}

// ---------------------------------------------------------------
// 0) prep: zero coeff + counters, convert W_post/W_last-lower -> bf16
// ---------------------------------------------------------------
__global__ void k_prep(const float* __restrict__ Wp, const float* __restrict__ Wl, int N) {
    int i = blockIdx.x*blockDim.x + threadIdx.x;
    if (i < KEIG*H) g_coeff[i] = 0.f;
    if (i < N)      g_count[i] = 0;
    if (i < NF*H)   g_Wph[i] = __float2bfloat16(Wp[i]);
    if (i < H*H)    g_Wlh[i] = __float2bfloat16(Wl[(size_t)H*H + i]);
}

// ---------------------------------------------------------------
// 1) CSR build: count edges per dst
// ---------------------------------------------------------------
__global__ void k_count(const int* __restrict__ ei, int E) {
    int e = blockIdx.x*blockDim.x + threadIdx.x;
    if (e < E) atomicAdd(&g_count[ei[E + e]], 1);
}

// 2a) per-1024-chunk local exclusive scan
__global__ void k_scan1(int N) {
    __shared__ int sh[1024];
    int t = threadIdx.x;
    int i = blockIdx.x*1024 + t;
    int v = (i < N) ? g_count[i] : 0;
    sh[t] = v;
    __syncthreads();
    for (int off = 1; off < 1024; off <<= 1) {
        int u = (t >= off) ? sh[t - off] : 0;
        __syncthreads();
        sh[t] += u;
        __syncthreads();
    }
    if (i < N) g_rowstart[i] = sh[t] - v;     // local exclusive
    if (t == 1023) g_bsum[blockIdx.x] = sh[1023];
}

// 2b) fused block-offset scan + materialize rowstart/cursor
__global__ void k_scan23(int nb, int N) {
    __shared__ int sh[64];
    int t = threadIdx.x;
    if (t < 64) sh[t] = (t < nb) ? g_bsum[t] : 0;
    __syncthreads();
    if (t == 0) {
        int acc = 0;
#pragma unroll
        for (int i = 0; i < 64; i++) { int v = sh[i]; sh[i] = acc; acc += v; }
        if (blockIdx.x == 0) g_rowstart[N] = acc;   // total = E
    }
    __syncthreads();
    int boff = sh[blockIdx.x];
    int i = blockIdx.x*1024 + t;
    if (i < N) {
        int v = g_rowstart[i] + boff;
        g_rowstart[i] = v;
        g_cursor[i]   = v;
    }
}

// 3) scatter edge ids into CSR order
__global__ void k_scatter(const int* __restrict__ ei, int E) {
    int e = blockIdx.x*blockDim.x + threadIdx.x;
    if (e < E) {
        int d = ei[E + e];
        int p = atomicAdd(&g_cursor[d], 1);
        g_eord[p] = e;
    }
}

// ---------------------------------------------------------------
// 4) coeff[K,H] = eigvec^T @ (deg * node_fts)
// ---------------------------------------------------------------
__global__ void k_coeff(const float* __restrict__ nf, const float* __restrict__ deg,
                        const float* __restrict__ vec, int N) {
    __shared__ float xs[8][H];
    __shared__ float vs[8][KEIG];
    int t  = threadIdx.x;
    int kk = t & 31;
    int hb = (t >> 5) << 4;           // 0..112 step 16
    float acc[16];
#pragma unroll
    for (int j = 0; j < 16; j++) acc[j] = 0.f;
    int nbase = blockIdx.x * 128;
    for (int stage = 0; stage < 16; stage++) {
        int n0 = nbase + stage * 8;
        for (int i = t; i < 8*H; i += 256) {
            int r = i >> 7, c = i & 127;
            int n = n0 + r;
            xs[r][c] = (n < N) ? nf[(size_t)n*H + c] * deg[n] : 0.f;
        }
        for (int i = t; i < 8*KEIG; i += 256) {
            int r = i >> 5, c = i & 31;
            int n = n0 + r;
            vs[r][c] = (n < N) ? vec[(size_t)n*KEIG + c] : 0.f;
        }
        __syncthreads();
#pragma unroll
        for (int r = 0; r < 8; r++) {
            float v = vs[r][kk];
#pragma unroll
            for (int j = 0; j < 16; j++) acc[j] += v * xs[r][hb + j];
        }
        __syncthreads();
    }
#pragma unroll
    for (int j = 0; j < 16; j++) atomicAdd(&g_coeff[kk*H + hb + j], acc[j]);
}

// ---------------------------------------------------------------
// 6) x = eigvec @ (coeff * exp(-lam*softplus(t))), 32 nodes/block
// ---------------------------------------------------------------
__global__ void k_x(const float* __restrict__ vec, const float* __restrict__ lam,
                    const float* __restrict__ dt, int N) {
    __shared__ float c2[KEIG*H];       // 16 KB
    __shared__ float vs[32][KEIG+1];
    __shared__ float s_t[H];
    __shared__ float s_lam[KEIG];
    int t = threadIdx.x;
    if (t < H) {
        float x = dt[t];
        s_t[t] = (x > 20.f) ? x : log1pf(expf(x));
    }
    if (t < KEIG) s_lam[t] = lam[t];
    __syncthreads();
    for (int i = t; i < KEIG*H; i += 256) {
        int k = i >> 7, h = i & 127;
        c2[i] = g_coeff[i] * expf(-s_lam[k] * s_t[h]);
    }
    int n0 = blockIdx.x * 32;
    for (int i = t; i < 32*KEIG; i += 256) {
        int r = i >> 5, c = i & 31;
        int n = n0 + r;
        vs[r][c] = (n < N) ? vec[(size_t)n*KEIG + c] : 0.f;
    }
    __syncthreads();
    int h = t & 127;
    int g = t >> 7;                    // 0..1, 16 nodes each
    float acc[16];
#pragma unroll
    for (int i = 0; i < 16; i++) acc[i] = 0.f;
#pragma unroll
    for (int k = 0; k < KEIG; k++) {
        float c = c2[k*H + h];
#pragma unroll
        for (int i = 0; i < 16; i++) acc[i] += vs[g*16 + i][k] * c;
    }
#pragma unroll
    for (int i = 0; i < 16; i++) {
        int n = n0 + g*16 + i;
        if (n < N) g_x[(size_t)n*H + h] = acc[i];
    }
}

// ---------------------------------------------------------------
// 7) aggregation: warp-per-node, float4 per lane, shfl-broadcast,
//    2x unrolled edge loop; node range [base, lim)
// ---------------------------------------------------------------
__device__ __forceinline__ void st_bf16x4(__nv_bfloat16* p, float4 v) {
    __nv_bfloat162 lo = __floats2bfloat162_rn(v.x, v.y);
    __nv_bfloat162 hi = __floats2bfloat162_rn(v.z, v.w);
    uint2 u;
    memcpy(&u.x, &lo, 4);
    memcpy(&u.y, &hi, 4);
    *(uint2*)p = u;
}

__global__ __launch_bounds__(256) void k_agg(
        const int* __restrict__ ei, const float* __restrict__ Fn,
        const float* __restrict__ Fdig, const float* __restrict__ degv,
        int base, int lim) {
    int warp = threadIdx.x >> 5, lane = threadIdx.x & 31;
    int n = base + blockIdx.x * 8 + warp;
    if (n >= lim) return;
    int beg = g_rowstart[n], end = g_rowstart[n+1];
    const float4* xrow = (const float4*)&g_x[(size_t)n*H];
    float4 xn = xrow[lane];

    float4 s  = {0.f,0.f,0.f,0.f};
    float4 mx = {-INFINITY,-INFINITY,-INFINITY,-INFINITY};
    float4 ws = {0.f,0.f,0.f,0.f};
    float4 fs = {0.f,0.f,0.f,0.f};
    float wsum = 0.f;

    for (int jb = beg; jb < end; jb += 32) {
        int cnt = min(32, end - jb);
        int   srcl = 0;
        float Fl   = 0.f;
        if (jb + lane < end) {
            int e = g_eord[jb + lane];
            srcl = ei[e];
            Fl   = Fn[e];
        }
        int jj = 0;
        for (; jj + 2 <= cnt; jj += 2) {
            int   src0 = __shfl_sync(0xffffffffu, srcl, jj);
            int   src1 = __shfl_sync(0xffffffffu, srcl, jj + 1);
            float F0   = __shfl_sync(0xffffffffu, Fl,   jj);
            float F1   = __shfl_sync(0xffffffffu, Fl,   jj + 1);
            float4 m0 = *(const float4*)&g_x[(size_t)src0*H + lane*4];
            float4 m1 = *(const float4*)&g_x[(size_t)src1*H + lane*4];
            float w0 = fabsf(F0), w1 = fabsf(F1);
            s.x += m0.x + m1.x; s.y += m0.y + m1.y;
            s.z += m0.z + m1.z; s.w += m0.w + m1.w;
            mx.x = fmaxf(mx.x, fmaxf(m0.x, m1.x));
            mx.y = fmaxf(mx.y, fmaxf(m0.y, m1.y));
            mx.z = fmaxf(mx.z, fmaxf(m0.z, m1.z));
            mx.w = fmaxf(mx.w, fmaxf(m0.w, m1.w));
            ws.x += w0*m0.x + w1*m1.x; ws.y += w0*m0.y + w1*m1.y;
            ws.z += w0*m0.z + w1*m1.z; ws.w += w0*m0.w + w1*m1.w;
            fs.x += F0*m0.x + F1*m1.x; fs.y += F0*m0.y + F1*m1.y;
            fs.z += F0*m0.z + F1*m1.z; fs.w += F0*m0.w + F1*m1.w;
            wsum += w0 + w1;
        }
        if (jj < cnt) {
            int   src = __shfl_sync(0xffffffffu, srcl, jj);
            float F   = __shfl_sync(0xffffffffu, Fl,   jj);
            float4 m0 = *(const float4*)&g_x[(size_t)src*H + lane*4];
            float w = fabsf(F);
            s.x += m0.x; s.y += m0.y; s.z += m0.z; s.w += m0.w;
            mx.x = fmaxf(mx.x, m0.x); mx.y = fmaxf(mx.y, m0.y);
            mx.z = fmaxf(mx.z, m0.z); mx.w = fmaxf(mx.w, m0.w);
            ws.x += w*m0.x; ws.y += w*m0.y; ws.z += w*m0.z; ws.w += w*m0.w;
            fs.x += F*m0.x; fs.y += F*m0.y; fs.z += F*m0.z; fs.w += F*m0.w;
            wsum += w;
        }
    }

    float deg = degv[n];
    float inv_deg = 1.f / deg;
    float inv_w   = 1.f / (wsum + 1e-8f);
    float fd  = Fdig[n];
    float amp = log1pf(deg) / AVG_D_LOG;
    bool has = (end > beg);

    float4 mean  = { s.x*inv_deg, s.y*inv_deg, s.z*inv_deg, s.w*inv_deg };
    float4 mxo   = { has ? mx.x : 0.f, has ? mx.y : 0.f,
                     has ? mx.z : 0.f, has ? mx.w : 0.f };
    float4 dirav = { ws.x*inv_w, ws.y*inv_w, ws.z*inv_w, ws.w*inv_w };
    float4 dirdx = { fs.x - fd*xn.x, fs.y - fd*xn.y,
                     fs.z - fd*xn.z, fs.w - fd*xn.w };

    __nv_bfloat16* bp2 = &g_featsh[(size_t)n*NF + lane*4];
    st_bf16x4(bp2 + 0*H, xn);
    st_bf16x4(bp2 + 1*H, mean);
    st_bf16x4(bp2 + 2*H, mxo);
    st_bf16x4(bp2 + 3*H, dirav);
    st_bf16x4(bp2 + 4*H, dirdx);
    float4 t;
    t = make_float4(mean.x*amp,  mean.y*amp,  mean.z*amp,  mean.w*amp);  st_bf16x4(bp2 + 5*H, t);
    t = make_float4(mxo.x*amp,   mxo.y*amp,   mxo.z*amp,   mxo.w*amp);   st_bf16x4(bp2 + 6*H, t);
    t = make_float4(dirav.x*amp, dirav.y*amp, dirav.z*amp, dirav.w*amp); st_bf16x4(bp2 + 7*H, t);
    t = make_float4(dirdx.x*amp, dirdx.y*amp, dirdx.z*amp, dirdx.w*amp); st_bf16x4(bp2 + 8*H, t);
}

// ---------------------------------------------------------------
// MMA helpers
// ---------------------------------------------------------------
__device__ __forceinline__ void ldm_x4(uint32_t* r, uint32_t addr) {
    asm volatile("ldmatrix.sync.aligned.m8n8.x4.shared.b16 {%0,%1,%2,%3}, [%4];"
        : "=r"(r[0]), "=r"(r[1]), "=r"(r[2]), "=r"(r[3]) : "r"(addr));
}
__device__ __forceinline__ void ldm_x4_t(uint32_t* r, uint32_t addr) {
    asm volatile("ldmatrix.sync.aligned.m8n8.x4.trans.shared.b16 {%0,%1,%2,%3}, [%4];"
        : "=r"(r[0]), "=r"(r[1]), "=r"(r[2]), "=r"(r[3]) : "r"(addr));
}
__device__ __forceinline__ void mma_bf16(float* d, const uint32_t* a, const uint32_t* b) {
    asm volatile(
        "mma.sync.aligned.m16n8k16.row.col.f32.bf16.bf16.f32 "
        "{%0,%1,%2,%3}, {%4,%5,%6,%7}, {%8,%9}, {%0,%1,%2,%3};"
        : "+f"(d[0]), "+f"(d[1]), "+f"(d[2]), "+f"(d[3])
        : "r"(a[0]), "r"(a[1]), "r"(a[2]), "r"(a[3]), "r"(b[0]), "r"(b[1]));
}
__device__ __forceinline__ void mma_tf32(float* d, const uint32_t* a, const uint32_t* b) {
    asm volatile(
        "mma.sync.aligned.m16n8k8.row.col.f32.tf32.tf32.f32 "
        "{%0,%1,%2,%3}, {%4,%5,%6,%7}, {%8,%9}, {%0,%1,%2,%3};"
        : "+f"(d[0]), "+f"(d[1]), "+f"(d[2]), "+f"(d[3])
        : "r"(a[0]), "r"(a[1]), "r"(a[2]), "r"(a[3]), "r"(b[0]), "r"(b[1]));
}
__device__ __forceinline__ uint32_t f2tf32(float x) {
    uint32_t o;
    asm("cvt.rna.tf32.f32 %0, %1;" : "=r"(o) : "f"(x));
    return o;
}
__device__ __forceinline__ void cp16(void* smem, const void* gmem) {
    uint32_t s = (uint32_t)__cvta_generic_to_shared(smem);
    asm volatile("cp.async.cg.shared.global [%0], [%1], 16;" :: "r"(s), "l"(gmem));
}

// ---------------------------------------------------------------
// 8) FUSED MLP (round-9 2-stage pipeline), row range [base, base+grid*128)
// ---------------------------------------------------------------
#define AST 40    // phase-1 A stride (bf16)
#define BST 136   // phase-1 B / Ds / Bs3 stride (bf16)
#define A2ST 36   // phase-2a A stride (tf32 words)
#define B2ST 136  // phase-2a B stride (tf32 words)

// dynamic smem layout (bytes)
#define SM_P1A 0                        // 2*128*AST*2  = 20480
#define SM_P1B 20480                    // 2*32*BST*2   = 17408  (end 37888)
#define SM_DS  0                        // 128*BST*2    = 34816  (after phase 1)
#define SM_AS2 34816                    // 128*A2ST*4   = 18432  (end 53248)
#define SM_BS2 53248                    // 32*B2ST*4    = 17408  (end 70656)
#define SM_BS3 34816                    // 128*BST*2    = 34816  (end 69632, after 2a)
#define SM_TOTAL 70656

__global__ __launch_bounds__(256) void k_mlp(
        const float* __restrict__ bp, const float* __restrict__ normn,
        const float* __restrict__ Wl, const float* __restrict__ bl,
        const float* __restrict__ nfts, float* __restrict__ out,
        int base, int N) {
    extern __shared__ char smem[];
    __nv_bfloat16* As  = (__nv_bfloat16*)(smem + SM_P1A);   // [2][128*AST]
    __nv_bfloat16* Bs  = (__nv_bfloat16*)(smem + SM_P1B);   // [2][32*BST]
    __nv_bfloat16* Ds  = (__nv_bfloat16*)(smem + SM_DS);    // [128*BST]
    uint32_t*      As2 = (uint32_t*)     (smem + SM_AS2);   // [128*A2ST]
    uint32_t*      Bs2 = (uint32_t*)     (smem + SM_BS2);   // [32*B2ST]
    __nv_bfloat16* Bs3 = (__nv_bfloat16*)(smem + SM_BS3);   // [128*BST]

    int t = threadIdx.x;
    int warp = t >> 5, lane = t & 31;
    int m0 = base + blockIdx.x * 128;
    int wm = warp >> 1;            // 0..3 -> 32 rows each
    int wn = warp & 1;             // 0..1 -> 64 cols each
    int lrow = lane & 15, lseg = (lane >> 4) * 8;
    int qrow = lane >> 2;          // 0..7
    int qcol = (lane & 3) * 2;     // 0,2,4,6

    float acc[2][8][4];
#pragma unroll
    for (int i = 0; i < 2; i++)
#pragma unroll
        for (int j = 0; j < 8; j++)
#pragma unroll
            for (int c = 0; c < 4; c++) acc[i][j][c] = 0.f;

    // ---------------- phase 1: feats @ W_post ----------------
    int arow = t >> 1, acol = (t & 1) * 16;    // A: 128 rows x 32 cols
    int brow = t >> 3, bcol = (t & 7) * 16;    // B: 32 rows x 128 cols
    const __nv_bfloat16* agbase = &g_featsh[(size_t)(m0 + arow)*NF + acol];
    const __nv_bfloat16* bgbase = &g_Wph[(size_t)brow*H + bcol];

#define P1_STAGE(s, k0) do {                                             \
        cp16(&As[(s)*128*AST + arow*AST + acol],     agbase + (k0));     \
        cp16(&As[(s)*128*AST + arow*AST + acol + 8], agbase + (k0) + 8); \
        cp16(&Bs[(s)*32*BST + brow*BST + bcol],      bgbase + (size_t)(k0)*H);     \
        cp16(&Bs[(s)*32*BST + brow*BST + bcol + 8],  bgbase + (size_t)(k0)*H + 8); \
        asm volatile("cp.async.commit_group;");                          \
    } while (0)

    const int NIT = NF / 32;   // 36
    P1_STAGE(0, 0);
    for (int it = 0; it < NIT; it++) {
        int st = it & 1;
        if (it + 1 < NIT) {
            P1_STAGE(1 - st, (it + 1) * 32);
            asm volatile("cp.async.wait_group 1;");
        } else {
            asm volatile("cp.async.wait_group 0;");
        }
        __syncthreads();
#pragma unroll
        for (int ks = 0; ks < 2; ks++) {
            int kk = ks * 16;
            uint32_t a[2][4], b[4][4];
#pragma unroll
            for (int tm = 0; tm < 2; tm++) {
                uint32_t addr = (uint32_t)__cvta_generic_to_shared(
                    &As[st*128*AST + (wm*32 + tm*16 + lrow)*AST + kk + lseg]);
                ldm_x4(a[tm], addr);
            }
#pragma unroll
            for (int tn = 0; tn < 4; tn++) {
                uint32_t addr = (uint32_t)__cvta_generic_to_shared(
                    &Bs[st*32*BST + (kk + lrow)*BST + wn*64 + tn*16 + lseg]);
                ldm_x4_t(b[tn], addr);
            }
#pragma unroll
            for (int tm = 0; tm < 2; tm++)
#pragma unroll
                for (int tn = 0; tn < 4; tn++) {
                    mma_bf16(acc[tm][tn*2],     a[tm], &b[tn][0]);
                    mma_bf16(acc[tm][tn*2 + 1], a[tm], &b[tn][2]);
                }
        }
        __syncthreads();
    }
#undef P1_STAGE

    // epilogue 1: bias + relu + graph-norm -> Ds (bf16, stride BST)
#pragma unroll
    for (int tm = 0; tm < 2; tm++) {
#pragma unroll
        for (int tnn = 0; tnn < 8; tnn++) {
            int col = wn*64 + tnn*8 + qcol;
            float bb0 = bp[col], bb1 = bp[col + 1];
            int r0 = m0 + wm*32 + tm*16 + qrow;
            int r1 = r0 + 8;
            int lr0 = wm*32 + tm*16 + qrow;
            float nn0 = (r0 < N) ? normn[r0] : 0.f;
            float nn1 = (r1 < N) ? normn[r1] : 0.f;
            __nv_bfloat162 v0 = __floats2bfloat162_rn(
                fmaxf(acc[tm][tnn][0] + bb0, 0.f) * nn0,
                fmaxf(acc[tm][tnn][1] + bb1, 0.f) * nn0);
            __nv_bfloat162 v1 = __floats2bfloat162_rn(
                fmaxf(acc[tm][tnn][2] + bb0, 0.f) * nn1,
                fmaxf(acc[tm][tnn][3] + bb1, 0.f) * nn1);
            *(__nv_bfloat162*)&Ds[lr0*BST + col]       = v0;
            *(__nv_bfloat162*)&Ds[(lr0 + 8)*BST + col] = v1;
        }
    }

    // reset accumulators for phase 2
#pragma unroll
    for (int i = 0; i < 2; i++)
#pragma unroll
        for (int j = 0; j < 8; j++)
#pragma unroll
            for (int c = 0; c < 4; c++) acc[i][j][c] = 0.f;
    __syncthreads();

    // ---------------- phase 2a: x @ Wl_top (tf32) ----------------
    int lr = lane >> 2, lc = lane & 3;
    for (int k0 = 0; k0 < H; k0 += 32) {
        const float* asrcp = &g_x[(size_t)(m0 + arow)*H + k0 + acol];
#pragma unroll
        for (int q = 0; q < 4; q++) {
            float4 v = *(const float4*)(asrcp + q*4);
            uint32_t* d = &As2[arow*A2ST + acol + q*4];
            d[0] = f2tf32(v.x); d[1] = f2tf32(v.y);
            d[2] = f2tf32(v.z); d[3] = f2tf32(v.w);
        }
        const float* bsrcp = &Wl[(size_t)(k0 + brow)*H + bcol];
#pragma unroll
        for (int q = 0; q < 4; q++) {
            float4 v = *(const float4*)(bsrcp + q*4);
            uint32_t* d = &Bs2[brow*B2ST + bcol + q*4];
            d[0] = f2tf32(v.x); d[1] = f2tf32(v.y);
            d[2] = f2tf32(v.z); d[3] = f2tf32(v.w);
        }
        __syncthreads();
#pragma unroll
        for (int ks = 0; ks < 4; ks++) {
            int ko = ks * 8;
            uint32_t a[2][4], b[8][2];
#pragma unroll
            for (int tm = 0; tm < 2; tm++) {
                int r = (wm*32 + tm*16 + lr) * A2ST;
                a[tm][0] = As2[r + ko + lc];
                a[tm][1] = As2[r + 8*A2ST + ko + lc];
                a[tm][2] = As2[r + ko + 4 + lc];
                a[tm][3] = As2[r + 8*A2ST + ko + 4 + lc];
            }
#pragma unroll
            for (int tn = 0; tn < 8; tn++) {
                int nn = wn*64 + tn*8 + lr;
                b[tn][0] = Bs2[(ko + lc)*B2ST + nn];
                b[tn][1] = Bs2[(ko + 4 + lc)*B2ST + nn];
            }
#pragma unroll
            for (int tm = 0; tm < 2; tm++)
#pragma unroll
                for (int tn = 0; tn < 8; tn++)
                    mma_tf32(acc[tm][tn], a[tm], b[tn]);
        }
        __syncthreads();
    }

    // ---------------- phase 2b: dgn @ Wl_bot (bf16, Ds in smem) ----------------
    // stage Wl_bot (bf16, 128x128 = 16 chunks of 8 bf16 per row) into Bs3
    for (int i = t; i < 128*16; i += 256) {
        int r = i >> 4, seg = (i & 15) * 8;
        cp16(&Bs3[r*BST + seg], &g_Wlh[r*H + seg]);
    }
    asm volatile("cp.async.commit_group;");
    asm volatile("cp.async.wait_group 0;");
    __syncthreads();

#pragma unroll
    for (int kk2 = 0; kk2 < 128; kk2 += 16) {
        uint32_t a[2][4], b[4][4];
#pragma unroll
        for (int tm = 0; tm < 2; tm++) {
            uint32_t addr = (uint32_t)__cvta_generic_to_shared(
                &Ds[(wm*32 + tm*16 + lrow)*BST + kk2 + lseg]);
            ldm_x4(a[tm], addr);
        }
#pragma unroll
        for (int tn = 0; tn < 4; tn++) {
            uint32_t addr = (uint32_t)__cvta_generic_to_shared(
                &Bs3[(kk2 + lrow)*BST + wn*64 + tn*16 + lseg]);
            ldm_x4_t(b[tn], addr);
        }
#pragma unroll
        for (int tm = 0; tm < 2; tm++)
#pragma unroll
            for (int tn = 0; tn < 4; tn++) {
                mma_bf16(acc[tm][tn*2],     a[tm], &b[tn][0]);
                mma_bf16(acc[tm][tn*2 + 1], a[tm], &b[tn][2]);
            }
    }

    // final epilogue: out = node_fts + acc + b_last
#pragma unroll
    for (int tm = 0; tm < 2; tm++) {
#pragma unroll
        for (int tn = 0; tn < 8; tn++) {
            int col = wn*64 + tn*8 + qcol;
            float bb0 = bl[col], bb1 = bl[col + 1];
            int r0 = m0 + wm*32 + tm*16 + qrow;
            int r1 = r0 + 8;
            if (r0 < N) {
                float2 rv = *(const float2*)&nfts[(size_t)r0*H + col];
                float2 v = { rv.x + acc[tm][tn][0] + bb0,
                             rv.y + acc[tm][tn][1] + bb1 };
                *(float2*)&out[(size_t)r0*H + col] = v;
            }
            if (r1 < N) {
                float2 rv = *(const float2*)&nfts[(size_t)r1*H + col];
                float2 v = { rv.x + acc[tm][tn][2] + bb0,
                             rv.y + acc[tm][tn][3] + bb1 };
                *(float2*)&out[(size_t)r1*H + col] = v;
            }
        }
    }
}

// ---------------------------------------------------------------
extern "C" void kernel_launch(void* const* d_in, const int* in_sizes, int n_in,
                              void* d_out, int out_size) {
    const float* node_fts = (const float*)d_in[0];
    // d_in[1] = edge_fts (unused)
    const int*   ei       = (const int*)  d_in[2];   // [2,E]: src row then dst row
    const float* Fn       = (const float*)d_in[3];   // [E,1]
    const float* Fdig     = (const float*)d_in[4];   // [N,1]
    const float* degv     = (const float*)d_in[5];   // [N,1]
    // d_in[6] node_deg_mat, d_in[7] lap_mat (unused)
    const float* lam      = (const float*)d_in[8];   // [K]
    const float* vec      = (const float*)d_in[9];   // [N,K]
    int o = (n_in >= 18) ? 1 : 0;
    const float* normn = (const float*)d_in[10 + o]; // [N,1]
    const float* dt    = (const float*)d_in[12 + o]; // [H]
    const float* Wp    = (const float*)d_in[13 + o]; // [9H,H]
    const float* bp    = (const float*)d_in[14 + o]; // [H]
    const float* Wl    = (const float*)d_in[15 + o]; // [2H,H]
    const float* bl    = (const float*)d_in[16 + o]; // [H]

    int E = in_sizes[3];   // F_norm_edge has E elements
    int N = in_sizes[4];   // F_dig has N elements
    float* out = (float*)d_out;

    // opt-in to >48KB dynamic smem (idempotent; not a stream op)
    cudaFuncSetAttribute(k_mlp, cudaFuncAttributeMaxDynamicSharedMemorySize, SM_TOTAL);

    const int TB = 256;
    int nb = (N + 1023) / 1024;

    bool mt = (g_s1 != nullptr) && (g_evFork != nullptr) && (g_evJoin != nullptr)
           && (g_evA != nullptr) && (g_evJoin2 != nullptr);
    cudaStream_t sA = mt ? g_s1 : (cudaStream_t)0;

    // common root
    k_prep    <<<(NF*H + TB - 1)/TB, TB>>>(Wp, Wl, N);

    if (mt) {
        cudaEventRecord(g_evFork, (cudaStream_t)0);
        cudaStreamWaitEvent(sA, g_evFork, 0);
    }

    // chain A (CSR build) — side stream
    k_count   <<<(E + TB - 1)/TB, TB, 0, sA>>>(ei, E);
    k_scan1   <<<nb, 1024, 0, sA>>>(N);
    k_scan23  <<<nb, 1024, 0, sA>>>(nb, N);
    k_scatter <<<(E + TB - 1)/TB, TB, 0, sA>>>(ei, E);
    if (mt) cudaEventRecord(g_evJoin, sA);

    // chain B (spectral diffusion) — main stream
    k_coeff   <<<(N + 127)/128, 256>>>(node_fts, degv, vec, N);
    k_x       <<<(N + 31)/32, 256>>>(vec, lam, dt, N);

    if (mt) cudaStreamWaitEvent((cudaStream_t)0, g_evJoin, 0);

    // split point: N1 = first half rounded up to 128 (mlp tile alignment)
    int N1 = ((N / 2 + 127) / 128) * 128;
    if (N1 > N) N1 = N;

    if (mt) {
        // half-pipelined tail: agg1 -> (agg2 || mlp1) -> mlp2
        k_agg <<<(N1 + 7)/8, 256>>>(ei, Fn, Fdig, degv, 0, N1);
        cudaEventRecord(g_evA, (cudaStream_t)0);
        k_agg <<<(N - N1 + 7)/8, 256>>>(ei, Fn, Fdig, degv, N1, N);

        cudaStreamWaitEvent(sA, g_evA, 0);
        k_mlp <<<N1/128, 256, SM_TOTAL, sA>>>(bp, normn, Wl, bl, node_fts, out, 0, N);
        cudaEventRecord(g_evJoin2, sA);

        k_mlp <<<(N - N1 + 127)/128, 256, SM_TOTAL>>>(bp, normn, Wl, bl, node_fts, out, N1, N);
        cudaStreamWaitEvent((cudaStream_t)0, g_evJoin2, 0);
    } else {
        k_agg <<<(N + 7)/8, 256>>>(ei, Fn, Fdig, degv, 0, N);
        k_mlp <<<(N + 127)/128, 256, SM_TOTAL>>>(bp, normn, Wl, bl, node_fts, out, 0, N);
    }
}

// round 15
// speedup vs baseline: 1.4607x; 1.0416x over previous
#include <cuda_runtime.h>
#include <cuda_bf16.h>
#include <math.h>
#include <stdint.h>
#include <string.h>

// Problem constants (shape-fixed by the dataset)
#define H    128
#define KEIG 32
#define NF   (9*H)           // 1152
#define MAXN 50048           // N=50000 rounded up to 64
#define MAXE 600064          // E=600000
#define AVG_D_LOG 2.5649493574615367f   // log(13)

// ---- static device scratch (no allocation allowed) ----
__device__ float g_x[(size_t)MAXN*H];               // diffusion_out (fp32, for mlp 2a)
__device__ __nv_bfloat16 g_xh[(size_t)MAXN*H];      // diffusion_out (bf16 mirror, for gather)
__device__ __nv_bfloat16 g_featsh[(size_t)MAXN*NF]; // [N,9H] concat features (bf16)
__device__ __nv_bfloat16 g_Wph[NF*H];               // W_post in bf16
__device__ __nv_bfloat16 g_Wlh[H*H];                // W_last lower half (rows H..2H) in bf16
__device__ float g_coeff[KEIG*H];
__device__ int   g_count[MAXN];
__device__ int   g_rowstart[MAXN+1];
__device__ int   g_cursor[MAXN];
__device__ int   g_eord[MAXE];
__device__ int   g_bsum[64];

// ---- persistent side stream + events ----
static cudaStream_t g_s1 = nullptr;
static cudaEvent_t  g_evFork = nullptr, g_evJoin = nullptr;
namespace {
struct StreamInit {
    StreamInit() {
        if (cudaStreamCreateWithFlags(&g_s1, cudaStreamNonBlocking) != cudaSuccess) g_s1 = nullptr;
        if (cudaEventCreateWithFlags(&g_evFork, cudaEventDisableTiming) != cudaSuccess) g_evFork = nullptr;
        if (cudaEventCreateWithFlags(&g_evJoin, cudaEventDisableTiming) != cudaSuccess) g_evJoin = nullptr;
    }
};
static StreamInit g_si;
}

// ---------------------------------------------------------------
// 0) prep: zero coeff + counters, convert W_post/W_last-lower -> bf16
// ---------------------------------------------------------------
__global__ void k_prep(const float* __restrict__ Wp, const float* __restrict__ Wl, int N) {
    int i = blockIdx.x*blockDim.x + threadIdx.x;
    if (i < KEIG*H) g_coeff[i] = 0.f;
    if (i < N)      g_count[i] = 0;
    if (i < NF*H)   g_Wph[i] = __float2bfloat16(Wp[i]);
    if (i < H*H)    g_Wlh[i] = __float2bfloat16(Wl[(size_t)H*H + i]);
}

// ---------------------------------------------------------------
// 1) CSR build: count edges per dst
// ---------------------------------------------------------------
__global__ void k_count(const int* __restrict__ ei, int E) {
    int e = blockIdx.x*blockDim.x + threadIdx.x;
    if (e < E) atomicAdd(&g_count[ei[E + e]], 1);
}

// 2a) per-1024-chunk local exclusive scan
__global__ void k_scan1(int N) {
    __shared__ int sh[1024];
    int t = threadIdx.x;
    int i = blockIdx.x*1024 + t;
    int v = (i < N) ? g_count[i] : 0;
    sh[t] = v;
    __syncthreads();
    for (int off = 1; off < 1024; off <<= 1) {
        int u = (t >= off) ? sh[t - off] : 0;
        __syncthreads();
        sh[t] += u;
        __syncthreads();
    }
    if (i < N) g_rowstart[i] = sh[t] - v;     // local exclusive
    if (t == 1023) g_bsum[blockIdx.x] = sh[1023];
}

// 2b) fused block-offset scan + materialize rowstart/cursor
__global__ void k_scan23(int nb, int N) {
    __shared__ int sh[64];
    int t = threadIdx.x;
    if (t < 64) sh[t] = (t < nb) ? g_bsum[t] : 0;
    __syncthreads();
    if (t == 0) {
        int acc = 0;
#pragma unroll
        for (int i = 0; i < 64; i++) { int v = sh[i]; sh[i] = acc; acc += v; }
        if (blockIdx.x == 0) g_rowstart[N] = acc;   // total = E
    }
    __syncthreads();
    int boff = sh[blockIdx.x];
    int i = blockIdx.x*1024 + t;
    if (i < N) {
        int v = g_rowstart[i] + boff;
        g_rowstart[i] = v;
        g_cursor[i]   = v;
    }
}

// 3) scatter edge ids into CSR order
__global__ void k_scatter(const int* __restrict__ ei, int E) {
    int e = blockIdx.x*blockDim.x + threadIdx.x;
    if (e < E) {
        int d = ei[E + e];
        int p = atomicAdd(&g_cursor[d], 1);
        g_eord[p] = e;
    }
}

// ---------------------------------------------------------------
// 4) coeff[K,H] = eigvec^T @ (deg * node_fts)
// ---------------------------------------------------------------
__global__ void k_coeff(const float* __restrict__ nf, const float* __restrict__ deg,
                        const float* __restrict__ vec, int N) {
    __shared__ float xs[8][H];
    __shared__ float vs[8][KEIG];
    int t  = threadIdx.x;
    int kk = t & 31;
    int hb = (t >> 5) << 4;           // 0..112 step 16
    float acc[16];
#pragma unroll
    for (int j = 0; j < 16; j++) acc[j] = 0.f;
    int nbase = blockIdx.x * 128;
    for (int stage = 0; stage < 16; stage++) {
        int n0 = nbase + stage * 8;
        for (int i = t; i < 8*H; i += 256) {
            int r = i >> 7, c = i & 127;
            int n = n0 + r;
            xs[r][c] = (n < N) ? nf[(size_t)n*H + c] * deg[n] : 0.f;
        }
        for (int i = t; i < 8*KEIG; i += 256) {
            int r = i >> 5, c = i & 31;
            int n = n0 + r;
            vs[r][c] = (n < N) ? vec[(size_t)n*KEIG + c] : 0.f;
        }
        __syncthreads();
#pragma unroll
        for (int r = 0; r < 8; r++) {
            float v = vs[r][kk];
#pragma unroll
            for (int j = 0; j < 16; j++) acc[j] += v * xs[r][hb + j];
        }
        __syncthreads();
    }
#pragma unroll
    for (int j = 0; j < 16; j++) atomicAdd(&g_coeff[kk*H + hb + j], acc[j]);
}

// ---------------------------------------------------------------
// 6) x = eigvec @ (coeff * exp(-lam*softplus(t))), 32 nodes/block
//    writes fp32 g_x AND bf16 mirror g_xh
// ---------------------------------------------------------------
__global__ void k_x(const float* __restrict__ vec, const float* __restrict__ lam,
                    const float* __restrict__ dt, int N) {
    __shared__ float c2[KEIG*H];       // 16 KB
    __shared__ float vs[32][KEIG+1];
    __shared__ float s_t[H];
    __shared__ float s_lam[KEIG];
    int t = threadIdx.x;
    if (t < H) {
        float x = dt[t];
        s_t[t] = (x > 20.f) ? x : log1pf(expf(x));
    }
    if (t < KEIG) s_lam[t] = lam[t];
    __syncthreads();
    for (int i = t; i < KEIG*H; i += 256) {
        int k = i >> 7, h = i & 127;
        c2[i] = g_coeff[i] * expf(-s_lam[k] * s_t[h]);
    }
    int n0 = blockIdx.x * 32;
    for (int i = t; i < 32*KEIG; i += 256) {
        int r = i >> 5, c = i & 31;
        int n = n0 + r;
        vs[r][c] = (n < N) ? vec[(size_t)n*KEIG + c] : 0.f;
    }
    __syncthreads();
    int h = t & 127;
    int g = t >> 7;                    // 0..1, 16 nodes each
    float acc[16];
#pragma unroll
    for (int i = 0; i < 16; i++) acc[i] = 0.f;
#pragma unroll
    for (int k = 0; k < KEIG; k++) {
        float c = c2[k*H + h];
#pragma unroll
        for (int i = 0; i < 16; i++) acc[i] += vs[g*16 + i][k] * c;
    }
#pragma unroll
    for (int i = 0; i < 16; i++) {
        int n = n0 + g*16 + i;
        if (n < N) {
            g_x [(size_t)n*H + h] = acc[i];
            g_xh[(size_t)n*H + h] = __float2bfloat16(acc[i]);
        }
    }
}

// ---------------------------------------------------------------
// 7) aggregation: warp-per-node, bf16 gather (8B/lane), shfl-
//    broadcast, 2x unrolled edge loop
// ---------------------------------------------------------------
__device__ __forceinline__ void st_bf16x4(__nv_bfloat16* p, float4 v) {
    __nv_bfloat162 lo = __floats2bfloat162_rn(v.x, v.y);
    __nv_bfloat162 hi = __floats2bfloat162_rn(v.z, v.w);
    uint2 u;
    memcpy(&u.x, &lo, 4);
    memcpy(&u.y, &hi, 4);
    *(uint2*)p = u;
}
__device__ __forceinline__ float4 ld_bf16x4(const __nv_bfloat16* p) {
    uint2 u = *(const uint2*)p;
    __nv_bfloat162 lo, hi;
    memcpy(&lo, &u.x, 4);
    memcpy(&hi, &u.y, 4);
    float2 a = __bfloat1622float2(lo);
    float2 b = __bfloat1622float2(hi);
    return make_float4(a.x, a.y, b.x, b.y);
}

__global__ __launch_bounds__(256) void k_agg(
        const int* __restrict__ ei, const float* __restrict__ Fn,
        const float* __restrict__ Fdig, const float* __restrict__ degv, int N) {
    int warp = threadIdx.x >> 5, lane = threadIdx.x & 31;
    int n = blockIdx.x * 8 + warp;
    if (n >= N) return;
    int beg = g_rowstart[n], end = g_rowstart[n+1];
    const float4* xrow = (const float4*)&g_x[(size_t)n*H];
    float4 xn = xrow[lane];

    float4 s  = {0.f,0.f,0.f,0.f};
    float4 mx = {-INFINITY,-INFINITY,-INFINITY,-INFINITY};
    float4 ws = {0.f,0.f,0.f,0.f};
    float4 fs = {0.f,0.f,0.f,0.f};
    float wsum = 0.f;

    for (int jb = beg; jb < end; jb += 32) {
        int cnt = min(32, end - jb);
        int   srcl = 0;
        float Fl   = 0.f;
        if (jb + lane < end) {
            int e = g_eord[jb + lane];
            srcl = ei[e];
            Fl   = Fn[e];
        }
        int jj = 0;
        for (; jj + 2 <= cnt; jj += 2) {
            int   src0 = __shfl_sync(0xffffffffu, srcl, jj);
            int   src1 = __shfl_sync(0xffffffffu, srcl, jj + 1);
            float F0   = __shfl_sync(0xffffffffu, Fl,   jj);
            float F1   = __shfl_sync(0xffffffffu, Fl,   jj + 1);
            float4 m0 = ld_bf16x4(&g_xh[(size_t)src0*H + lane*4]);
            float4 m1 = ld_bf16x4(&g_xh[(size_t)src1*H + lane*4]);
            float w0 = fabsf(F0), w1 = fabsf(F1);
            s.x += m0.x + m1.x; s.y += m0.y + m1.y;
            s.z += m0.z + m1.z; s.w += m0.w + m1.w;
            mx.x = fmaxf(mx.x, fmaxf(m0.x, m1.x));
            mx.y = fmaxf(mx.y, fmaxf(m0.y, m1.y));
            mx.z = fmaxf(mx.z, fmaxf(m0.z, m1.z));
            mx.w = fmaxf(mx.w, fmaxf(m0.w, m1.w));
            ws.x += w0*m0.x + w1*m1.x; ws.y += w0*m0.y + w1*m1.y;
            ws.z += w0*m0.z + w1*m1.z; ws.w += w0*m0.w + w1*m1.w;
            fs.x += F0*m0.x + F1*m1.x; fs.y += F0*m0.y + F1*m1.y;
            fs.z += F0*m0.z + F1*m1.z; fs.w += F0*m0.w + F1*m1.w;
            wsum += w0 + w1;
        }
        if (jj < cnt) {
            int   src = __shfl_sync(0xffffffffu, srcl, jj);
            float F   = __shfl_sync(0xffffffffu, Fl,   jj);
            float4 m0 = ld_bf16x4(&g_xh[(size_t)src*H + lane*4]);
            float w = fabsf(F);
            s.x += m0.x; s.y += m0.y; s.z += m0.z; s.w += m0.w;
            mx.x = fmaxf(mx.x, m0.x); mx.y = fmaxf(mx.y, m0.y);
            mx.z = fmaxf(mx.z, m0.z); mx.w = fmaxf(mx.w, m0.w);
            ws.x += w*m0.x; ws.y += w*m0.y; ws.z += w*m0.z; ws.w += w*m0.w;
            fs.x += F*m0.x; fs.y += F*m0.y; fs.z += F*m0.z; fs.w += F*m0.w;
            wsum += w;
        }
    }

    float deg = degv[n];
    float inv_deg = 1.f / deg;
    float inv_w   = 1.f / (wsum + 1e-8f);
    float fd  = Fdig[n];
    float amp = log1pf(deg) / AVG_D_LOG;
    bool has = (end > beg);

    float4 mean  = { s.x*inv_deg, s.y*inv_deg, s.z*inv_deg, s.w*inv_deg };
    float4 mxo   = { has ? mx.x : 0.f, has ? mx.y : 0.f,
                     has ? mx.z : 0.f, has ? mx.w : 0.f };
    float4 dirav = { ws.x*inv_w, ws.y*inv_w, ws.z*inv_w, ws.w*inv_w };
    float4 dirdx = { fs.x - fd*xn.x, fs.y - fd*xn.y,
                     fs.z - fd*xn.z, fs.w - fd*xn.w };

    __nv_bfloat16* base = &g_featsh[(size_t)n*NF + lane*4];
    st_bf16x4(base + 0*H, xn);
    st_bf16x4(base + 1*H, mean);
    st_bf16x4(base + 2*H, mxo);
    st_bf16x4(base + 3*H, dirav);
    st_bf16x4(base + 4*H, dirdx);
    float4 t;
    t = make_float4(mean.x*amp,  mean.y*amp,  mean.z*amp,  mean.w*amp);  st_bf16x4(base + 5*H, t);
    t = make_float4(mxo.x*amp,   mxo.y*amp,   mxo.z*amp,   mxo.w*amp);   st_bf16x4(base + 6*H, t);
    t = make_float4(dirav.x*amp, dirav.y*amp, dirav.z*amp, dirav.w*amp); st_bf16x4(base + 7*H, t);
    t = make_float4(dirdx.x*amp, dirdx.y*amp, dirdx.z*amp, dirdx.w*amp); st_bf16x4(base + 8*H, t);
}

// ---------------------------------------------------------------
// MMA helpers
// ---------------------------------------------------------------
__device__ __forceinline__ void ldm_x4(uint32_t* r, uint32_t addr) {
    asm volatile("ldmatrix.sync.aligned.m8n8.x4.shared.b16 {%0,%1,%2,%3}, [%4];"
        : "=r"(r[0]), "=r"(r[1]), "=r"(r[2]), "=r"(r[3]) : "r"(addr));
}
__device__ __forceinline__ void ldm_x4_t(uint32_t* r, uint32_t addr) {
    asm volatile("ldmatrix.sync.aligned.m8n8.x4.trans.shared.b16 {%0,%1,%2,%3}, [%4];"
        : "=r"(r[0]), "=r"(r[1]), "=r"(r[2]), "=r"(r[3]) : "r"(addr));
}
__device__ __forceinline__ void mma_bf16(float* d, const uint32_t* a, const uint32_t* b) {
    asm volatile(
        "mma.sync.aligned.m16n8k16.row.col.f32.bf16.bf16.f32 "
        "{%0,%1,%2,%3}, {%4,%5,%6,%7}, {%8,%9}, {%0,%1,%2,%3};"
        : "+f"(d[0]), "+f"(d[1]), "+f"(d[2]), "+f"(d[3])
        : "r"(a[0]), "r"(a[1]), "r"(a[2]), "r"(a[3]), "r"(b[0]), "r"(b[1]));
}
__device__ __forceinline__ void mma_tf32(float* d, const uint32_t* a, const uint32_t* b) {
    asm volatile(
        "mma.sync.aligned.m16n8k8.row.col.f32.tf32.tf32.f32 "
        "{%0,%1,%2,%3}, {%4,%5,%6,%7}, {%8,%9}, {%0,%1,%2,%3};"
        : "+f"(d[0]), "+f"(d[1]), "+f"(d[2]), "+f"(d[3])
        : "r"(a[0]), "r"(a[1]), "r"(a[2]), "r"(a[3]), "r"(b[0]), "r"(b[1]));
}
__device__ __forceinline__ uint32_t f2tf32(float x) {
    uint32_t o;
    asm("cvt.rna.tf32.f32 %0, %1;" : "=r"(o) : "f"(x));
    return o;
}
__device__ __forceinline__ void cp16(void* smem, const void* gmem) {
    uint32_t s = (uint32_t)__cvta_generic_to_shared(smem);
    asm volatile("cp.async.cg.shared.global [%0], [%1], 16;" :: "r"(s), "l"(gmem));
}

// ---------------------------------------------------------------
// 8) FUSED MLP (round-9 known-good 2-stage pipeline):
//    phase 1: dgn = relu(feats @ W_post + b_post)*norm_n -> smem (bf16)
//    phase 2a: acc = x @ Wl_top (tf32 TC, from gmem)
//    phase 2b: acc += dgn @ Wl_bot (bf16 TC, dgn from smem)
//    out = node_fts + acc + b_last
// ---------------------------------------------------------------
#define AST 40    // phase-1 A stride (bf16)
#define BST 136   // phase-1 B / Ds / Bs3 stride (bf16)
#define A2ST 36   // phase-2a A stride (tf32 words)
#define B2ST 136  // phase-2a B stride (tf32 words)

// dynamic smem layout (bytes)
#define SM_P1A 0                        // 2*128*AST*2  = 20480
#define SM_P1B 20480                    // 2*32*BST*2   = 17408  (end 37888)
#define SM_DS  0                        // 128*BST*2    = 34816  (after phase 1)
#define SM_AS2 34816                    // 128*A2ST*4   = 18432  (end 53248)
#define SM_BS2 53248                    // 32*B2ST*4    = 17408  (end 70656)
#define SM_BS3 34816                    // 128*BST*2    = 34816  (end 69632, after 2a)
#define SM_TOTAL 70656

__global__ __launch_bounds__(256) void k_mlp(
        const float* __restrict__ bp, const float* __restrict__ normn,
        const float* __restrict__ Wl, const float* __restrict__ bl,
        const float* __restrict__ nfts, float* __restrict__ out, int N) {
    extern __shared__ char smem[];
    __nv_bfloat16* As  = (__nv_bfloat16*)(smem + SM_P1A);   // [2][128*AST]
    __nv_bfloat16* Bs  = (__nv_bfloat16*)(smem + SM_P1B);   // [2][32*BST]
    __nv_bfloat16* Ds  = (__nv_bfloat16*)(smem + SM_DS);    // [128*BST]
    uint32_t*      As2 = (uint32_t*)     (smem + SM_AS2);   // [128*A2ST]
    uint32_t*      Bs2 = (uint32_t*)     (smem + SM_BS2);   // [32*B2ST]
    __nv_bfloat16* Bs3 = (__nv_bfloat16*)(smem + SM_BS3);   // [128*BST]

    int t = threadIdx.x;
    int warp = t >> 5, lane = t & 31;
    int m0 = blockIdx.x * 128;
    int wm = warp >> 1;            // 0..3 -> 32 rows each
    int wn = warp & 1;             // 0..1 -> 64 cols each
    int lrow = lane & 15, lseg = (lane >> 4) * 8;
    int qrow = lane >> 2;          // 0..7
    int qcol = (lane & 3) * 2;     // 0,2,4,6

    float acc[2][8][4];
#pragma unroll
    for (int i = 0; i < 2; i++)
#pragma unroll
        for (int j = 0; j < 8; j++)
#pragma unroll
            for (int c = 0; c < 4; c++) acc[i][j][c] = 0.f;

    // ---------------- phase 1: feats @ W_post ----------------
    int arow = t >> 1, acol = (t & 1) * 16;    // A: 128 rows x 32 cols
    int brow = t >> 3, bcol = (t & 7) * 16;    // B: 32 rows x 128 cols
    const __nv_bfloat16* agbase = &g_featsh[(size_t)(m0 + arow)*NF + acol];
    const __nv_bfloat16* bgbase = &g_Wph[(size_t)brow*H + bcol];

#define P1_STAGE(s, k0) do {                                             \
        cp16(&As[(s)*128*AST + arow*AST + acol],     agbase + (k0));     \
        cp16(&As[(s)*128*AST + arow*AST + acol + 8], agbase + (k0) + 8); \
        cp16(&Bs[(s)*32*BST + brow*BST + bcol],      bgbase + (size_t)(k0)*H);     \
        cp16(&Bs[(s)*32*BST + brow*BST + bcol + 8],  bgbase + (size_t)(k0)*H + 8); \
        asm volatile("cp.async.commit_group;");                          \
    } while (0)

    const int NIT = NF / 32;   // 36
    P1_STAGE(0, 0);
    for (int it = 0; it < NIT; it++) {
        int st = it & 1;
        if (it + 1 < NIT) {
            P1_STAGE(1 - st, (it + 1) * 32);
            asm volatile("cp.async.wait_group 1;");
        } else {
            asm volatile("cp.async.wait_group 0;");
        }
        __syncthreads();
#pragma unroll
        for (int ks = 0; ks < 2; ks++) {
            int kk = ks * 16;
            uint32_t a[2][4], b[4][4];
#pragma unroll
            for (int tm = 0; tm < 2; tm++) {
                uint32_t addr = (uint32_t)__cvta_generic_to_shared(
                    &As[st*128*AST + (wm*32 + tm*16 + lrow)*AST + kk + lseg]);
                ldm_x4(a[tm], addr);
            }
#pragma unroll
            for (int tn = 0; tn < 4; tn++) {
                uint32_t addr = (uint32_t)__cvta_generic_to_shared(
                    &Bs[st*32*BST + (kk + lrow)*BST + wn*64 + tn*16 + lseg]);
                ldm_x4_t(b[tn], addr);
            }
#pragma unroll
            for (int tm = 0; tm < 2; tm++)
#pragma unroll
                for (int tn = 0; tn < 4; tn++) {
                    mma_bf16(acc[tm][tn*2],     a[tm], &b[tn][0]);
                    mma_bf16(acc[tm][tn*2 + 1], a[tm], &b[tn][2]);
                }
        }
        __syncthreads();
    }
#undef P1_STAGE

    // epilogue 1: bias + relu + graph-norm -> Ds (bf16, stride BST)
#pragma unroll
    for (int tm = 0; tm < 2; tm++) {
#pragma unroll
        for (int tnn = 0; tnn < 8; tnn++) {
            int col = wn*64 + tnn*8 + qcol;
            float bb0 = bp[col], bb1 = bp[col + 1];
            int r0 = m0 + wm*32 + tm*16 + qrow;
            int r1 = r0 + 8;
            int lr0 = wm*32 + tm*16 + qrow;
            float nn0 = (r0 < N) ? normn[r0] : 0.f;
            float nn1 = (r1 < N) ? normn[r1] : 0.f;
            __nv_bfloat162 v0 = __floats2bfloat162_rn(
                fmaxf(acc[tm][tnn][0] + bb0, 0.f) * nn0,
                fmaxf(acc[tm][tnn][1] + bb1, 0.f) * nn0);
            __nv_bfloat162 v1 = __floats2bfloat162_rn(
                fmaxf(acc[tm][tnn][2] + bb0, 0.f) * nn1,
                fmaxf(acc[tm][tnn][3] + bb1, 0.f) * nn1);
            *(__nv_bfloat162*)&Ds[lr0*BST + col]       = v0;
            *(__nv_bfloat162*)&Ds[(lr0 + 8)*BST + col] = v1;
        }
    }

    // reset accumulators for phase 2
#pragma unroll
    for (int i = 0; i < 2; i++)
#pragma unroll
        for (int j = 0; j < 8; j++)
#pragma unroll
            for (int c = 0; c < 4; c++) acc[i][j][c] = 0.f;
    __syncthreads();

    // ---------------- phase 2a: x @ Wl_top (tf32) ----------------
    int lr = lane >> 2, lc = lane & 3;
    for (int k0 = 0; k0 < H; k0 += 32) {
        const float* asrcp = &g_x[(size_t)(m0 + arow)*H + k0 + acol];
#pragma unroll
        for (int q = 0; q < 4; q++) {
            float4 v = *(const float4*)(asrcp + q*4);
            uint32_t* d = &As2[arow*A2ST + acol + q*4];
            d[0] = f2tf32(v.x); d[1] = f2tf32(v.y);
            d[2] = f2tf32(v.z); d[3] = f2tf32(v.w);
        }
        const float* bsrcp = &Wl[(size_t)(k0 + brow)*H + bcol];
#pragma unroll
        for (int q = 0; q < 4; q++) {
            float4 v = *(const float4*)(bsrcp + q*4);
            uint32_t* d = &Bs2[brow*B2ST + bcol + q*4];
            d[0] = f2tf32(v.x); d[1] = f2tf32(v.y);
            d[2] = f2tf32(v.z); d[3] = f2tf32(v.w);
        }
        __syncthreads();
#pragma unroll
        for (int ks = 0; ks < 4; ks++) {
            int ko = ks * 8;
            uint32_t a[2][4], b[8][2];
#pragma unroll
            for (int tm = 0; tm < 2; tm++) {
                int r = (wm*32 + tm*16 + lr) * A2ST;
                a[tm][0] = As2[r + ko + lc];
                a[tm][1] = As2[r + 8*A2ST + ko + lc];
                a[tm][2] = As2[r + ko + 4 + lc];
                a[tm][3] = As2[r + 8*A2ST + ko + 4 + lc];
            }
#pragma unroll
            for (int tn = 0; tn < 8; tn++) {
                int nn = wn*64 + tn*8 + lr;
                b[tn][0] = Bs2[(ko + lc)*B2ST + nn];
                b[tn][1] = Bs2[(ko + 4 + lc)*B2ST + nn];
            }
#pragma unroll
            for (int tm = 0; tm < 2; tm++)
#pragma unroll
                for (int tn = 0; tn < 8; tn++)
                    mma_tf32(acc[tm][tn], a[tm], b[tn]);
        }
        __syncthreads();
    }

    // ---------------- phase 2b: dgn @ Wl_bot (bf16, Ds in smem) ----------------
    // stage Wl_bot (bf16, 128x128 = 16 chunks of 8 bf16 per row) into Bs3
    for (int i = t; i < 128*16; i += 256) {
        int r = i >> 4, seg = (i & 15) * 8;
        cp16(&Bs3[r*BST + seg], &g_Wlh[r*H + seg]);
    }
    asm volatile("cp.async.commit_group;");
    asm volatile("cp.async.wait_group 0;");
    __syncthreads();

#pragma unroll
    for (int kk2 = 0; kk2 < 128; kk2 += 16) {
        uint32_t a[2][4], b[4][4];
#pragma unroll
        for (int tm = 0; tm < 2; tm++) {
            uint32_t addr = (uint32_t)__cvta_generic_to_shared(
                &Ds[(wm*32 + tm*16 + lrow)*BST + kk2 + lseg]);
            ldm_x4(a[tm], addr);
        }
#pragma unroll
        for (int tn = 0; tn < 4; tn++) {
            uint32_t addr = (uint32_t)__cvta_generic_to_shared(
                &Bs3[(kk2 + lrow)*BST + wn*64 + tn*16 + lseg]);
            ldm_x4_t(b[tn], addr);
        }
#pragma unroll
        for (int tm = 0; tm < 2; tm++)
#pragma unroll
            for (int tn = 0; tn < 4; tn++) {
                mma_bf16(acc[tm][tn*2],     a[tm], &b[tn][0]);
                mma_bf16(acc[tm][tn*2 + 1], a[tm], &b[tn][2]);
            }
    }

    // final epilogue: out = node_fts + acc + b_last
#pragma unroll
    for (int tm = 0; tm < 2; tm++) {
#pragma unroll
        for (int tn = 0; tn < 8; tn++) {
            int col = wn*64 + tn*8 + qcol;
            float bb0 = bl[col], bb1 = bl[col + 1];
            int r0 = m0 + wm*32 + tm*16 + qrow;
            int r1 = r0 + 8;
            if (r0 < N) {
                float2 rv = *(const float2*)&nfts[(size_t)r0*H + col];
                float2 v = { rv.x + acc[tm][tn][0] + bb0,
                             rv.y + acc[tm][tn][1] + bb1 };
                *(float2*)&out[(size_t)r0*H + col] = v;
            }
            if (r1 < N) {
                float2 rv = *(const float2*)&nfts[(size_t)r1*H + col];
                float2 v = { rv.x + acc[tm][tn][2] + bb0,
                             rv.y + acc[tm][tn][3] + bb1 };
                *(float2*)&out[(size_t)r1*H + col] = v;
            }
        }
    }
}

// ---------------------------------------------------------------
extern "C" void kernel_launch(void* const* d_in, const int* in_sizes, int n_in,
                              void* d_out, int out_size) {
    const float* node_fts = (const float*)d_in[0];
    // d_in[1] = edge_fts (unused)
    const int*   ei       = (const int*)  d_in[2];   // [2,E]: src row then dst row
    const float* Fn       = (const float*)d_in[3];   // [E,1]
    const float* Fdig     = (const float*)d_in[4];   // [N,1]
    const float* degv     = (const float*)d_in[5];   // [N,1]
    // d_in[6] node_deg_mat, d_in[7] lap_mat (unused)
    const float* lam      = (const float*)d_in[8];   // [K]
    const float* vec      = (const float*)d_in[9];   // [N,K]
    int o = (n_in >= 18) ? 1 : 0;
    const float* normn = (const float*)d_in[10 + o]; // [N,1]
    const float* dt    = (const float*)d_in[12 + o]; // [H]
    const float* Wp    = (const float*)d_in[13 + o]; // [9H,H]
    const float* bp    = (const float*)d_in[14 + o]; // [H]
    const float* Wl    = (const float*)d_in[15 + o]; // [2H,H]
    const float* bl    = (const float*)d_in[16 + o]; // [H]

    int E = in_sizes[3];   // F_norm_edge has E elements
    int N = in_sizes[4];   // F_dig has N elements
    float* out = (float*)d_out;

    // opt-in to >48KB dynamic smem (idempotent; not a stream op)
    cudaFuncSetAttribute(k_mlp, cudaFuncAttributeMaxDynamicSharedMemorySize, SM_TOTAL);

    const int TB = 256;
    int nb = (N + 1023) / 1024;

    bool mt = (g_s1 != nullptr) && (g_evFork != nullptr) && (g_evJoin != nullptr);
    cudaStream_t sA = mt ? g_s1 : (cudaStream_t)0;

    // common root
    k_prep    <<<(NF*H + TB - 1)/TB, TB>>>(Wp, Wl, N);

    if (mt) {
        cudaEventRecord(g_evFork, (cudaStream_t)0);
        cudaStreamWaitEvent(sA, g_evFork, 0);
    }

    // chain A (CSR build) — side stream
    k_count   <<<(E + TB - 1)/TB, TB, 0, sA>>>(ei, E);
    k_scan1   <<<nb, 1024, 0, sA>>>(N);
    k_scan23  <<<nb, 1024, 0, sA>>>(nb, N);
    k_scatter <<<(E + TB - 1)/TB, TB, 0, sA>>>(ei, E);
    if (mt) cudaEventRecord(g_evJoin, sA);

    // chain B (spectral diffusion) — main stream
    k_coeff   <<<(N + 127)/128, 256>>>(node_fts, degv, vec, N);
    k_x       <<<(N + 31)/32, 256>>>(vec, lam, dt, N);

    if (mt) cudaStreamWaitEvent((cudaStream_t)0, g_evJoin, 0);

    // join: aggregation + fused MLP
    k_agg     <<<(N + 7)/8, 256>>>(ei, Fn, Fdig, degv, N);
    k_mlp     <<<(N + 127)/128, 256, SM_TOTAL>>>(bp, normn, Wl, bl, node_fts, out, N);
}

// round 16
// speedup vs baseline: 1.4833x; 1.0154x over previous
#include <cuda_runtime.h>
#include <cuda_bf16.h>
#include <math.h>
#include <stdint.h>
#include <string.h>

// Problem constants (shape-fixed by the dataset)
#define H    128
#define KEIG 32
#define NF   (9*H)           // 1152
#define MAXN 50048           // N=50000 rounded up to 64
#define MAXE 600064          // E=600000
#define AVG_D_LOG 2.5649493574615367f   // log(13)

// ---- static device scratch (no allocation allowed) ----
__device__ float g_x[(size_t)MAXN*H];               // diffusion_out (fp32, for mlp 2a)
__device__ __nv_bfloat16 g_xh[(size_t)MAXN*H];      // diffusion_out (bf16 mirror, for gather)
__device__ __nv_bfloat16 g_featsh[(size_t)MAXN*NF]; // [N,9H] concat features (bf16)
__device__ __nv_bfloat16 g_Wph[NF*H];               // W_post in bf16
__device__ __nv_bfloat16 g_Wlh[H*H];                // W_last lower half (rows H..2H) in bf16
__device__ float g_coeff[KEIG*H];
__device__ int   g_count[MAXN];
__device__ int   g_rowstart[MAXN+1];
__device__ int   g_cursor[MAXN];
__device__ int2  g_epack[MAXE];                     // CSR-ordered {src, F-bits}
__device__ int   g_bsum[64];

// ---- persistent side stream + events ----
static cudaStream_t g_s1 = nullptr;
static cudaEvent_t  g_evFork = nullptr, g_evJoin = nullptr;
namespace {
struct StreamInit {
    StreamInit() {
        if (cudaStreamCreateWithFlags(&g_s1, cudaStreamNonBlocking) != cudaSuccess) g_s1 = nullptr;
        if (cudaEventCreateWithFlags(&g_evFork, cudaEventDisableTiming) != cudaSuccess) g_evFork = nullptr;
        if (cudaEventCreateWithFlags(&g_evJoin, cudaEventDisableTiming) != cudaSuccess) g_evJoin = nullptr;
    }
};
static StreamInit g_si;
}

// ---------------------------------------------------------------
// 0) prep: zero coeff + counters, convert W_post/W_last-lower -> bf16
// ---------------------------------------------------------------
__global__ void k_prep(const float* __restrict__ Wp, const float* __restrict__ Wl, int N) {
    int i = blockIdx.x*blockDim.x + threadIdx.x;
    if (i < KEIG*H) g_coeff[i] = 0.f;
    if (i < N)      g_count[i] = 0;
    if (i < NF*H)   g_Wph[i] = __float2bfloat16(Wp[i]);
    if (i < H*H)    g_Wlh[i] = __float2bfloat16(Wl[(size_t)H*H + i]);
}

// ---------------------------------------------------------------
// 1) CSR build: count edges per dst
// ---------------------------------------------------------------
__global__ void k_count(const int* __restrict__ ei, int E) {
    int e = blockIdx.x*blockDim.x + threadIdx.x;
    if (e < E) atomicAdd(&g_count[ei[E + e]], 1);
}

// 2a) per-1024-chunk local exclusive scan
__global__ void k_scan1(int N) {
    __shared__ int sh[1024];
    int t = threadIdx.x;
    int i = blockIdx.x*1024 + t;
    int v = (i < N) ? g_count[i] : 0;
    sh[t] = v;
    __syncthreads();
    for (int off = 1; off < 1024; off <<= 1) {
        int u = (t >= off) ? sh[t - off] : 0;
        __syncthreads();
        sh[t] += u;
        __syncthreads();
    }
    if (i < N) g_rowstart[i] = sh[t] - v;     // local exclusive
    if (t == 1023) g_bsum[blockIdx.x] = sh[1023];
}

// 2b) fused block-offset scan + materialize rowstart/cursor
__global__ void k_scan23(int nb, int N) {
    __shared__ int sh[64];
    int t = threadIdx.x;
    if (t < 64) sh[t] = (t < nb) ? g_bsum[t] : 0;
    __syncthreads();
    if (t == 0) {
        int acc = 0;
#pragma unroll
        for (int i = 0; i < 64; i++) { int v = sh[i]; sh[i] = acc; acc += v; }
        if (blockIdx.x == 0) g_rowstart[N] = acc;   // total = E
    }
    __syncthreads();
    int boff = sh[blockIdx.x];
    int i = blockIdx.x*1024 + t;
    if (i < N) {
        int v = g_rowstart[i] + boff;
        g_rowstart[i] = v;
        g_cursor[i]   = v;
    }
}

// 3) scatter packed edge metadata {src, F} into CSR order
__global__ void k_scatter(const int* __restrict__ ei, const float* __restrict__ Fn, int E) {
    int e = blockIdx.x*blockDim.x + threadIdx.x;
    if (e < E) {
        int d = ei[E + e];
        int p = atomicAdd(&g_cursor[d], 1);
        g_epack[p] = make_int2(ei[e], __float_as_int(Fn[e]));
    }
}

// ---------------------------------------------------------------
// 4) coeff[K,H] = eigvec^T @ (deg * node_fts)
// ---------------------------------------------------------------
__global__ void k_coeff(const float* __restrict__ nf, const float* __restrict__ deg,
                        const float* __restrict__ vec, int N) {
    __shared__ float xs[8][H];
    __shared__ float vs[8][KEIG];
    int t  = threadIdx.x;
    int kk = t & 31;
    int hb = (t >> 5) << 4;           // 0..112 step 16
    float acc[16];
#pragma unroll
    for (int j = 0; j < 16; j++) acc[j] = 0.f;
    int nbase = blockIdx.x * 128;
    for (int stage = 0; stage < 16; stage++) {
        int n0 = nbase + stage * 8;
        for (int i = t; i < 8*H; i += 256) {
            int r = i >> 7, c = i & 127;
            int n = n0 + r;
            xs[r][c] = (n < N) ? nf[(size_t)n*H + c] * deg[n] : 0.f;
        }
        for (int i = t; i < 8*KEIG; i += 256) {
            int r = i >> 5, c = i & 31;
            int n = n0 + r;
            vs[r][c] = (n < N) ? vec[(size_t)n*KEIG + c] : 0.f;
        }
        __syncthreads();
#pragma unroll
        for (int r = 0; r < 8; r++) {
            float v = vs[r][kk];
#pragma unroll
            for (int j = 0; j < 16; j++) acc[j] += v * xs[r][hb + j];
        }
        __syncthreads();
    }
#pragma unroll
    for (int j = 0; j < 16; j++) atomicAdd(&g_coeff[kk*H + hb + j], acc[j]);
}

// ---------------------------------------------------------------
// 6) x = eigvec @ (coeff * exp(-lam*softplus(t))), 32 nodes/block
//    writes fp32 g_x AND bf16 mirror g_xh
// ---------------------------------------------------------------
__global__ void k_x(const float* __restrict__ vec, const float* __restrict__ lam,
                    const float* __restrict__ dt, int N) {
    __shared__ float c2[KEIG*H];       // 16 KB
    __shared__ float vs[32][KEIG+1];
    __shared__ float s_t[H];
    __shared__ float s_lam[KEIG];
    int t = threadIdx.x;
    if (t < H) {
        float x = dt[t];
        s_t[t] = (x > 20.f) ? x : log1pf(expf(x));
    }
    if (t < KEIG) s_lam[t] = lam[t];
    __syncthreads();
    for (int i = t; i < KEIG*H; i += 256) {
        int k = i >> 7, h = i & 127;
        c2[i] = g_coeff[i] * expf(-s_lam[k] * s_t[h]);
    }
    int n0 = blockIdx.x * 32;
    for (int i = t; i < 32*KEIG; i += 256) {
        int r = i >> 5, c = i & 31;
        int n = n0 + r;
        vs[r][c] = (n < N) ? vec[(size_t)n*KEIG + c] : 0.f;
    }
    __syncthreads();
    int h = t & 127;
    int g = t >> 7;                    // 0..1, 16 nodes each
    float acc[16];
#pragma unroll
    for (int i = 0; i < 16; i++) acc[i] = 0.f;
#pragma unroll
    for (int k = 0; k < KEIG; k++) {
        float c = c2[k*H + h];
#pragma unroll
        for (int i = 0; i < 16; i++) acc[i] += vs[g*16 + i][k] * c;
    }
#pragma unroll
    for (int i = 0; i < 16; i++) {
        int n = n0 + g*16 + i;
        if (n < N) {
            g_x [(size_t)n*H + h] = acc[i];
            g_xh[(size_t)n*H + h] = __float2bfloat16(acc[i]);
        }
    }
}

// ---------------------------------------------------------------
// 7) aggregation: warp-per-node, bf16 gather (8B/lane), packed
//    edge metadata, shfl-broadcast, 2x unrolled edge loop
// ---------------------------------------------------------------
__device__ __forceinline__ void st_bf16x4(__nv_bfloat16* p, float4 v) {
    __nv_bfloat162 lo = __floats2bfloat162_rn(v.x, v.y);
    __nv_bfloat162 hi = __floats2bfloat162_rn(v.z, v.w);
    uint2 u;
    memcpy(&u.x, &lo, 4);
    memcpy(&u.y, &hi, 4);
    *(uint2*)p = u;
}
__device__ __forceinline__ float4 ld_bf16x4(const __nv_bfloat16* p) {
    uint2 u = *(const uint2*)p;
    __nv_bfloat162 lo, hi;
    memcpy(&lo, &u.x, 4);
    memcpy(&hi, &u.y, 4);
    float2 a = __bfloat1622float2(lo);
    float2 b = __bfloat1622float2(hi);
    return make_float4(a.x, a.y, b.x, b.y);
}

__global__ __launch_bounds__(256) void k_agg(
        const float* __restrict__ Fdig, const float* __restrict__ degv, int N) {
    int warp = threadIdx.x >> 5, lane = threadIdx.x & 31;
    int n = blockIdx.x * 8 + warp;
    if (n >= N) return;
    int beg = g_rowstart[n], end = g_rowstart[n+1];
    const float4* xrow = (const float4*)&g_x[(size_t)n*H];
    float4 xn = xrow[lane];

    float4 s  = {0.f,0.f,0.f,0.f};
    float4 mx = {-INFINITY,-INFINITY,-INFINITY,-INFINITY};
    float4 ws = {0.f,0.f,0.f,0.f};
    float4 fs = {0.f,0.f,0.f,0.f};
    float wsum = 0.f;

    for (int jb = beg; jb < end; jb += 32) {
        int cnt = min(32, end - jb);
        int   srcl = 0;
        float Fl   = 0.f;
        if (jb + lane < end) {
            int2 pk = g_epack[jb + lane];
            srcl = pk.x;
            Fl   = __int_as_float(pk.y);
        }
        int jj = 0;
        for (; jj + 2 <= cnt; jj += 2) {
            int   src0 = __shfl_sync(0xffffffffu, srcl, jj);
            int   src1 = __shfl_sync(0xffffffffu, srcl, jj + 1);
            float F0   = __shfl_sync(0xffffffffu, Fl,   jj);
            float F1   = __shfl_sync(0xffffffffu, Fl,   jj + 1);
            float4 m0 = ld_bf16x4(&g_xh[(size_t)src0*H + lane*4]);
            float4 m1 = ld_bf16x4(&g_xh[(size_t)src1*H + lane*4]);
            float w0 = fabsf(F0), w1 = fabsf(F1);
            s.x += m0.x + m1.x; s.y += m0.y + m1.y;
            s.z += m0.z + m1.z; s.w += m0.w + m1.w;
            mx.x = fmaxf(mx.x, fmaxf(m0.x, m1.x));
            mx.y = fmaxf(mx.y, fmaxf(m0.y, m1.y));
            mx.z = fmaxf(mx.z, fmaxf(m0.z, m1.z));
            mx.w = fmaxf(mx.w, fmaxf(m0.w, m1.w));
            ws.x += w0*m0.x + w1*m1.x; ws.y += w0*m0.y + w1*m1.y;
            ws.z += w0*m0.z + w1*m1.z; ws.w += w0*m0.w + w1*m1.w;
            fs.x += F0*m0.x + F1*m1.x; fs.y += F0*m0.y + F1*m1.y;
            fs.z += F0*m0.z + F1*m1.z; fs.w += F0*m0.w + F1*m1.w;
            wsum += w0 + w1;
        }
        if (jj < cnt) {
            int   src = __shfl_sync(0xffffffffu, srcl, jj);
            float F   = __shfl_sync(0xffffffffu, Fl,   jj);
            float4 m0 = ld_bf16x4(&g_xh[(size_t)src*H + lane*4]);
            float w = fabsf(F);
            s.x += m0.x; s.y += m0.y; s.z += m0.z; s.w += m0.w;
            mx.x = fmaxf(mx.x, m0.x); mx.y = fmaxf(mx.y, m0.y);
            mx.z = fmaxf(mx.z, m0.z); mx.w = fmaxf(mx.w, m0.w);
            ws.x += w*m0.x; ws.y += w*m0.y; ws.z += w*m0.z; ws.w += w*m0.w;
            fs.x += F*m0.x; fs.y += F*m0.y; fs.z += F*m0.z; fs.w += F*m0.w;
            wsum += w;
        }
    }

    float deg = degv[n];
    float inv_deg = 1.f / deg;
    float inv_w   = 1.f / (wsum + 1e-8f);
    float fd  = Fdig[n];
    float amp = log1pf(deg) / AVG_D_LOG;
    bool has = (end > beg);

    float4 mean  = { s.x*inv_deg, s.y*inv_deg, s.z*inv_deg, s.w*inv_deg };
    float4 mxo   = { has ? mx.x : 0.f, has ? mx.y : 0.f,
                     has ? mx.z : 0.f, has ? mx.w : 0.f };
    float4 dirav = { ws.x*inv_w, ws.y*inv_w, ws.z*inv_w, ws.w*inv_w };
    float4 dirdx = { fs.x - fd*xn.x, fs.y - fd*xn.y,
                     fs.z - fd*xn.z, fs.w - fd*xn.w };

    __nv_bfloat16* base = &g_featsh[(size_t)n*NF + lane*4];
    st_bf16x4(base + 0*H, xn);
    st_bf16x4(base + 1*H, mean);
    st_bf16x4(base + 2*H, mxo);
    st_bf16x4(base + 3*H, dirav);
    st_bf16x4(base + 4*H, dirdx);
    float4 t;
    t = make_float4(mean.x*amp,  mean.y*amp,  mean.z*amp,  mean.w*amp);  st_bf16x4(base + 5*H, t);
    t = make_float4(mxo.x*amp,   mxo.y*amp,   mxo.z*amp,   mxo.w*amp);   st_bf16x4(base + 6*H, t);
    t = make_float4(dirav.x*amp, dirav.y*amp, dirav.z*amp, dirav.w*amp); st_bf16x4(base + 7*H, t);
    t = make_float4(dirdx.x*amp, dirdx.y*amp, dirdx.z*amp, dirdx.w*amp); st_bf16x4(base + 8*H, t);
}

// ---------------------------------------------------------------
// MMA helpers
// ---------------------------------------------------------------
__device__ __forceinline__ void ldm_x4(uint32_t* r, uint32_t addr) {
    asm volatile("ldmatrix.sync.aligned.m8n8.x4.shared.b16 {%0,%1,%2,%3}, [%4];"
        : "=r"(r[0]), "=r"(r[1]), "=r"(r[2]), "=r"(r[3]) : "r"(addr));
}
__device__ __forceinline__ void ldm_x4_t(uint32_t* r, uint32_t addr) {
    asm volatile("ldmatrix.sync.aligned.m8n8.x4.trans.shared.b16 {%0,%1,%2,%3}, [%4];"
        : "=r"(r[0]), "=r"(r[1]), "=r"(r[2]), "=r"(r[3]) : "r"(addr));
}
__device__ __forceinline__ void mma_bf16(float* d, const uint32_t* a, const uint32_t* b) {
    asm volatile(
        "mma.sync.aligned.m16n8k16.row.col.f32.bf16.bf16.f32 "
        "{%0,%1,%2,%3}, {%4,%5,%6,%7}, {%8,%9}, {%0,%1,%2,%3};"
        : "+f"(d[0]), "+f"(d[1]), "+f"(d[2]), "+f"(d[3])
        : "r"(a[0]), "r"(a[1]), "r"(a[2]), "r"(a[3]), "r"(b[0]), "r"(b[1]));
}
__device__ __forceinline__ void mma_tf32(float* d, const uint32_t* a, const uint32_t* b) {
    asm volatile(
        "mma.sync.aligned.m16n8k8.row.col.f32.tf32.tf32.f32 "
        "{%0,%1,%2,%3}, {%4,%5,%6,%7}, {%8,%9}, {%0,%1,%2,%3};"
        : "+f"(d[0]), "+f"(d[1]), "+f"(d[2]), "+f"(d[3])
        : "r"(a[0]), "r"(a[1]), "r"(a[2]), "r"(a[3]), "r"(b[0]), "r"(b[1]));
}
__device__ __forceinline__ uint32_t f2tf32(float x) {
    uint32_t o;
    asm("cvt.rna.tf32.f32 %0, %1;" : "=r"(o) : "f"(x));
    return o;
}
__device__ __forceinline__ void cp16(void* smem, const void* gmem) {
    uint32_t s = (uint32_t)__cvta_generic_to_shared(smem);
    asm volatile("cp.async.cg.shared.global [%0], [%1], 16;" :: "r"(s), "l"(gmem));
}

// ---------------------------------------------------------------
// 8) FUSED MLP (round-9 known-good 2-stage pipeline):
//    phase 1: dgn = relu(feats @ W_post + b_post)*norm_n -> smem (bf16)
//    phase 2a: acc = x @ Wl_top (tf32 TC, from gmem)
//    phase 2b: acc += dgn @ Wl_bot (bf16 TC, dgn from smem)
//    out = node_fts + acc + b_last
// ---------------------------------------------------------------
#define AST 40    // phase-1 A stride (bf16)
#define BST 136   // phase-1 B / Ds / Bs3 stride (bf16)
#define A2ST 36   // phase-2a A stride (tf32 words)
#define B2ST 136  // phase-2a B stride (tf32 words)

// dynamic smem layout (bytes)
#define SM_P1A 0                        // 2*128*AST*2  = 20480
#define SM_P1B 20480                    // 2*32*BST*2   = 17408  (end 37888)
#define SM_DS  0                        // 128*BST*2    = 34816  (after phase 1)
#define SM_AS2 34816                    // 128*A2ST*4   = 18432  (end 53248)
#define SM_BS2 53248                    // 32*B2ST*4    = 17408  (end 70656)
#define SM_BS3 34816                    // 128*BST*2    = 34816  (end 69632, after 2a)
#define SM_TOTAL 70656

__global__ __launch_bounds__(256) void k_mlp(
        const float* __restrict__ bp, const float* __restrict__ normn,
        const float* __restrict__ Wl, const float* __restrict__ bl,
        const float* __restrict__ nfts, float* __restrict__ out, int N) {
    extern __shared__ char smem[];
    __nv_bfloat16* As  = (__nv_bfloat16*)(smem + SM_P1A);   // [2][128*AST]
    __nv_bfloat16* Bs  = (__nv_bfloat16*)(smem + SM_P1B);   // [2][32*BST]
    __nv_bfloat16* Ds  = (__nv_bfloat16*)(smem + SM_DS);    // [128*BST]
    uint32_t*      As2 = (uint32_t*)     (smem + SM_AS2);   // [128*A2ST]
    uint32_t*      Bs2 = (uint32_t*)     (smem + SM_BS2);   // [32*B2ST]
    __nv_bfloat16* Bs3 = (__nv_bfloat16*)(smem + SM_BS3);   // [128*BST]

    int t = threadIdx.x;
    int warp = t >> 5, lane = t & 31;
    int m0 = blockIdx.x * 128;
    int wm = warp >> 1;            // 0..3 -> 32 rows each
    int wn = warp & 1;             // 0..1 -> 64 cols each
    int lrow = lane & 15, lseg = (lane >> 4) * 8;
    int qrow = lane >> 2;          // 0..7
    int qcol = (lane & 3) * 2;     // 0,2,4,6

    float acc[2][8][4];
#pragma unroll
    for (int i = 0; i < 2; i++)
#pragma unroll
        for (int j = 0; j < 8; j++)
#pragma unroll
            for (int c = 0; c < 4; c++) acc[i][j][c] = 0.f;

    // ---------------- phase 1: feats @ W_post ----------------
    int arow = t >> 1, acol = (t & 1) * 16;    // A: 128 rows x 32 cols
    int brow = t >> 3, bcol = (t & 7) * 16;    // B: 32 rows x 128 cols
    const __nv_bfloat16* agbase = &g_featsh[(size_t)(m0 + arow)*NF + acol];
    const __nv_bfloat16* bgbase = &g_Wph[(size_t)brow*H + bcol];

#define P1_STAGE(s, k0) do {                                             \
        cp16(&As[(s)*128*AST + arow*AST + acol],     agbase + (k0));     \
        cp16(&As[(s)*128*AST + arow*AST + acol + 8], agbase + (k0) + 8); \
        cp16(&Bs[(s)*32*BST + brow*BST + bcol],      bgbase + (size_t)(k0)*H);     \
        cp16(&Bs[(s)*32*BST + brow*BST + bcol + 8],  bgbase + (size_t)(k0)*H + 8); \
        asm volatile("cp.async.commit_group;");                          \
    } while (0)

    const int NIT = NF / 32;   // 36
    P1_STAGE(0, 0);
    for (int it = 0; it < NIT; it++) {
        int st = it & 1;
        if (it + 1 < NIT) {
            P1_STAGE(1 - st, (it + 1) * 32);
            asm volatile("cp.async.wait_group 1;");
        } else {
            asm volatile("cp.async.wait_group 0;");
        }
        __syncthreads();
#pragma unroll
        for (int ks = 0; ks < 2; ks++) {
            int kk = ks * 16;
            uint32_t a[2][4], b[4][4];
#pragma unroll
            for (int tm = 0; tm < 2; tm++) {
                uint32_t addr = (uint32_t)__cvta_generic_to_shared(
                    &As[st*128*AST + (wm*32 + tm*16 + lrow)*AST + kk + lseg]);
                ldm_x4(a[tm], addr);
            }
#pragma unroll
            for (int tn = 0; tn < 4; tn++) {
                uint32_t addr = (uint32_t)__cvta_generic_to_shared(
                    &Bs[st*32*BST + (kk + lrow)*BST + wn*64 + tn*16 + lseg]);
                ldm_x4_t(b[tn], addr);
            }
#pragma unroll
            for (int tm = 0; tm < 2; tm++)
#pragma unroll
                for (int tn = 0; tn < 4; tn++) {
                    mma_bf16(acc[tm][tn*2],     a[tm], &b[tn][0]);
                    mma_bf16(acc[tm][tn*2 + 1], a[tm], &b[tn][2]);
                }
        }
        __syncthreads();
    }
#undef P1_STAGE

    // epilogue 1: bias + relu + graph-norm -> Ds (bf16, stride BST)
#pragma unroll
    for (int tm = 0; tm < 2; tm++) {
#pragma unroll
        for (int tnn = 0; tnn < 8; tnn++) {
            int col = wn*64 + tnn*8 + qcol;
            float bb0 = bp[col], bb1 = bp[col + 1];
            int r0 = m0 + wm*32 + tm*16 + qrow;
            int r1 = r0 + 8;
            int lr0 = wm*32 + tm*16 + qrow;
            float nn0 = (r0 < N) ? normn[r0] : 0.f;
            float nn1 = (r1 < N) ? normn[r1] : 0.f;
            __nv_bfloat162 v0 = __floats2bfloat162_rn(
                fmaxf(acc[tm][tnn][0] + bb0, 0.f) * nn0,
                fmaxf(acc[tm][tnn][1] + bb1, 0.f) * nn0);
            __nv_bfloat162 v1 = __floats2bfloat162_rn(
                fmaxf(acc[tm][tnn][2] + bb0, 0.f) * nn1,
                fmaxf(acc[tm][tnn][3] + bb1, 0.f) * nn1);
            *(__nv_bfloat162*)&Ds[lr0*BST + col]       = v0;
            *(__nv_bfloat162*)&Ds[(lr0 + 8)*BST + col] = v1;
        }
    }

    // reset accumulators for phase 2
#pragma unroll
    for (int i = 0; i < 2; i++)
#pragma unroll
        for (int j = 0; j < 8; j++)
#pragma unroll
            for (int c = 0; c < 4; c++) acc[i][j][c] = 0.f;
    __syncthreads();

    // ---------------- phase 2a: x @ Wl_top (tf32) ----------------
    int lr = lane >> 2, lc = lane & 3;
    for (int k0 = 0; k0 < H; k0 += 32) {
        const float* asrcp = &g_x[(size_t)(m0 + arow)*H + k0 + acol];
#pragma unroll
        for (int q = 0; q < 4; q++) {
            float4 v = *(const float4*)(asrcp + q*4);
            uint32_t* d = &As2[arow*A2ST + acol + q*4];
            d[0] = f2tf32(v.x); d[1] = f2tf32(v.y);
            d[2] = f2tf32(v.z); d[3] = f2tf32(v.w);
        }
        const float* bsrcp = &Wl[(size_t)(k0 + brow)*H + bcol];
#pragma unroll
        for (int q = 0; q < 4; q++) {
            float4 v = *(const float4*)(bsrcp + q*4);
            uint32_t* d = &Bs2[brow*B2ST + bcol + q*4];
            d[0] = f2tf32(v.x); d[1] = f2tf32(v.y);
            d[2] = f2tf32(v.z); d[3] = f2tf32(v.w);
        }
        __syncthreads();
#pragma unroll
        for (int ks = 0; ks < 4; ks++) {
            int ko = ks * 8;
            uint32_t a[2][4], b[8][2];
#pragma unroll
            for (int tm = 0; tm < 2; tm++) {
                int r = (wm*32 + tm*16 + lr) * A2ST;
                a[tm][0] = As2[r + ko + lc];
                a[tm][1] = As2[r + 8*A2ST + ko + lc];
                a[tm][2] = As2[r + ko + 4 + lc];
                a[tm][3] = As2[r + 8*A2ST + ko + 4 + lc];
            }
#pragma unroll
            for (int tn = 0; tn < 8; tn++) {
                int nn = wn*64 + tn*8 + lr;
                b[tn][0] = Bs2[(ko + lc)*B2ST + nn];
                b[tn][1] = Bs2[(ko + 4 + lc)*B2ST + nn];
            }
#pragma unroll
            for (int tm = 0; tm < 2; tm++)
#pragma unroll
                for (int tn = 0; tn < 8; tn++)
                    mma_tf32(acc[tm][tn], a[tm], b[tn]);
        }
        __syncthreads();
    }

    // ---------------- phase 2b: dgn @ Wl_bot (bf16, Ds in smem) ----------------
    // stage Wl_bot (bf16, 128x128 = 16 chunks of 8 bf16 per row) into Bs3
    for (int i = t; i < 128*16; i += 256) {
        int r = i >> 4, seg = (i & 15) * 8;
        cp16(&Bs3[r*BST + seg], &g_Wlh[r*H + seg]);
    }
    asm volatile("cp.async.commit_group;");
    asm volatile("cp.async.wait_group 0;");
    __syncthreads();

#pragma unroll
    for (int kk2 = 0; kk2 < 128; kk2 += 16) {
        uint32_t a[2][4], b[4][4];
#pragma unroll
        for (int tm = 0; tm < 2; tm++) {
            uint32_t addr = (uint32_t)__cvta_generic_to_shared(
                &Ds[(wm*32 + tm*16 + lrow)*BST + kk2 + lseg]);
            ldm_x4(a[tm], addr);
        }
#pragma unroll
        for (int tn = 0; tn < 4; tn++) {
            uint32_t addr = (uint32_t)__cvta_generic_to_shared(
                &Bs3[(kk2 + lrow)*BST + wn*64 + tn*16 + lseg]);
            ldm_x4_t(b[tn], addr);
        }
#pragma unroll
        for (int tm = 0; tm < 2; tm++)
#pragma unroll
            for (int tn = 0; tn < 4; tn++) {
                mma_bf16(acc[tm][tn*2],     a[tm], &b[tn][0]);
                mma_bf16(acc[tm][tn*2 + 1], a[tm], &b[tn][2]);
            }
    }

    // final epilogue: out = node_fts + acc + b_last
#pragma unroll
    for (int tm = 0; tm < 2; tm++) {
#pragma unroll
        for (int tn = 0; tn < 8; tn++) {
            int col = wn*64 + tn*8 + qcol;
            float bb0 = bl[col], bb1 = bl[col + 1];
            int r0 = m0 + wm*32 + tm*16 + qrow;
            int r1 = r0 + 8;
            if (r0 < N) {
                float2 rv = *(const float2*)&nfts[(size_t)r0*H + col];
                float2 v = { rv.x + acc[tm][tn][0] + bb0,
                             rv.y + acc[tm][tn][1] + bb1 };
                *(float2*)&out[(size_t)r0*H + col] = v;
            }
            if (r1 < N) {
                float2 rv = *(const float2*)&nfts[(size_t)r1*H + col];
                float2 v = { rv.x + acc[tm][tn][2] + bb0,
                             rv.y + acc[tm][tn][3] + bb1 };
                *(float2*)&out[(size_t)r1*H + col] = v;
            }
        }
    }
}

// ---------------------------------------------------------------
extern "C" void kernel_launch(void* const* d_in, const int* in_sizes, int n_in,
                              void* d_out, int out_size) {
    const float* node_fts = (const float*)d_in[0];
    // d_in[1] = edge_fts (unused)
    const int*   ei       = (const int*)  d_in[2];   // [2,E]: src row then dst row
    const float* Fn       = (const float*)d_in[3];   // [E,1]
    const float* Fdig     = (const float*)d_in[4];   // [N,1]
    const float* degv     = (const float*)d_in[5];   // [N,1]
    // d_in[6] node_deg_mat, d_in[7] lap_mat (unused)
    const float* lam      = (const float*)d_in[8];   // [K]
    const float* vec      = (const float*)d_in[9];   // [N,K]
    int o = (n_in >= 18) ? 1 : 0;
    const float* normn = (const float*)d_in[10 + o]; // [N,1]
    const float* dt    = (const float*)d_in[12 + o]; // [H]
    const float* Wp    = (const float*)d_in[13 + o]; // [9H,H]
    const float* bp    = (const float*)d_in[14 + o]; // [H]
    const float* Wl    = (const float*)d_in[15 + o]; // [2H,H]
    const float* bl    = (const float*)d_in[16 + o]; // [H]

    int E = in_sizes[3];   // F_norm_edge has E elements
    int N = in_sizes[4];   // F_dig has N elements
    float* out = (float*)d_out;

    // opt-in to >48KB dynamic smem (idempotent; not a stream op)
    cudaFuncSetAttribute(k_mlp, cudaFuncAttributeMaxDynamicSharedMemorySize, SM_TOTAL);

    const int TB = 256;
    int nb = (N + 1023) / 1024;

    bool mt = (g_s1 != nullptr) && (g_evFork != nullptr) && (g_evJoin != nullptr);
    cudaStream_t sA = mt ? g_s1 : (cudaStream_t)0;

    // common root
    k_prep    <<<(NF*H + TB - 1)/TB, TB>>>(Wp, Wl, N);

    if (mt) {
        cudaEventRecord(g_evFork, (cudaStream_t)0);
        cudaStreamWaitEvent(sA, g_evFork, 0);
    }

    // chain A (CSR build) — side stream
    k_count   <<<(E + TB - 1)/TB, TB, 0, sA>>>(ei, E);
    k_scan1   <<<nb, 1024, 0, sA>>>(N);
    k_scan23  <<<nb, 1024, 0, sA>>>(nb, N);
    k_scatter <<<(E + TB - 1)/TB, TB, 0, sA>>>(ei, Fn, E);
    if (mt) cudaEventRecord(g_evJoin, sA);

    // chain B (spectral diffusion) — main stream
    k_coeff   <<<(N + 127)/128, 256>>>(node_fts, degv, vec, N);
    k_x       <<<(N + 31)/32, 256>>>(vec, lam, dt, N);

    if (mt) cudaStreamWaitEvent((cudaStream_t)0, g_evJoin, 0);

    // join: aggregation + fused MLP
    k_agg     <<<(N + 7)/8, 256>>>(Fdig, degv, N);
    k_mlp     <<<(N + 127)/128, 256, SM_TOTAL>>>(bp, normn, Wl, bl, node_fts, out, N);
}